// round 1
// baseline (speedup 1.0000x reference)
#include <cuda_runtime.h>

// ---------------------------------------------------------------------------
// StateTransformerBlock on GB300 — round 1: tf32 mma.sync GEMM pipeline.
// B=4, S_STATE=512, S_IN=1536, T=2048, D=1024, H=8, F=4096. All fp32 I/O.
// ---------------------------------------------------------------------------

#define DEV_INLINE __device__ __forceinline__

namespace stb {

constexpr int Bn      = 4;
constexpr int S_ST    = 512;
constexpr int S_INP   = 1536;
constexpr int Tn      = 2048;   // S_ST + S_INP
constexpr int Dn      = 1024;
constexpr int Hn      = 8;
constexpr int Fn      = 4096;

// ---------------- scratch (device globals; no allocation allowed) ----------
__device__ __align__(128) float g_k  [Bn * Tn * Dn];            // 33.5 MB
__device__ __align__(128) float g_v  [Bn * Tn * Dn];            // 33.5 MB
__device__ __align__(128) float g_q  [Bn * Hn * S_ST * Dn];     // 67 MB
__device__ __align__(128) float g_s  [(long long)Bn * Hn * S_ST * Tn]; // 134 MB
__device__ __align__(128) float g_cat[Bn * S_ST * Hn * Dn];     // 67 MB
__device__ __align__(128) float g_t1 [Bn * S_ST * Dn];          // 8 MB (attn_out, then ff)
__device__ __align__(128) float g_x  [Bn * S_ST * Dn];          // 8 MB
__device__ __align__(128) float g_in [Bn * S_ST * Fn];          // 33.5 MB
__device__ __align__(128) float g_g1 [Bn * S_ST * Fn];          // 33.5 MB
__device__ __align__(128) float g_g2 [Bn * S_ST * Fn];          // 33.5 MB

// ---------------- GEMM config ----------------------------------------------
constexpr int BM = 128, BN = 128, BK = 16;
constexpr int PAD = 8;
constexpr int LDA_S = BM + PAD;   // 136 words: frag loads bank-conflict-free
constexpr int LDB_S = BN + PAD;

enum { AMODE_DIRECT = 0, AMODE_CONCAT = 1 };
enum { BMODE_N = 0, BMODE_T = 1 };    // N: B[k][n] n-contig;  T: B[n][k] k-contig

DEV_INLINE unsigned f2tf(float x) {
    unsigned r;
    asm("cvt.rna.tf32.f32 %0, %1;" : "=r"(r) : "f"(x));
    return r;
}

// A is row-major [M,K] (or CONCAT-gathered rows of length 1024).
// BMODE_N: B row-major [K,N] (ldb = row stride). BMODE_T: element (k,n) at B[n*ldb + k].
// C row-major [M,N], ldc. Batched over blockIdx.z: z -> (zb = z/ZH, zh = z%ZH).
template <int AM, int BMODE, bool RELU>
__global__ void __launch_bounds__(256, 2)
gemm_tf32(const float* __restrict__ A, const float* __restrict__ A2,
          const float* __restrict__ Bmat, const float* __restrict__ bias,
          float* __restrict__ C,
          int M, int N, int K, int lda, int ldb, int ldc, int ZH,
          long long aSB, long long aSH, long long bSB, long long bSH,
          long long cSB, long long cSH, long long biasSH, float scale)
{
    __shared__ __align__(16) unsigned As[2][BK][LDA_S];
    __shared__ __align__(16) unsigned Bs[2][BK][LDB_S];

    const int z  = blockIdx.z;
    const int zb = z / ZH, zh = z - zb * ZH;
    const float* Ab = A    + zb * aSB + zh * aSH;
    const float* Bb = Bmat + zb * bSB + zh * bSH;
    float*       Cb = C    + zb * cSB + zh * cSH;
    const float* biasb = bias ? (bias + zh * biasSH) : (const float*)0;

    const int m0 = blockIdx.y * BM;
    const int n0 = blockIdx.x * BN;
    const int tid  = threadIdx.x;
    const int lane = tid & 31;
    const int warp = tid >> 5;
    const int wm = warp & 1;          // 2 warps along M (64 rows each)
    const int wn = warp >> 1;         // 4 warps along N (32 cols each)
    const int g   = lane >> 2;        // groupID 0..7
    const int tig = lane & 3;         // threadInGroup 0..3

    // staging maps
    const int arow = tid & 127;       // A/B(T) row/col, conflict-free STS
    const int akv  = tid >> 7;        // 0..1
    const int bcv  = tid & 31;        // B(N) float4 column
    const int brow = tid >> 5;        // B(N) k-row 0..7

    // A row base pointer (constant across the k loop)
    const float* aRow;
    if (AM == AMODE_CONCAT) {
        const int m = m0 + arow;
        const int b = m >> 11;        // / 2048
        const int t = m & 2047;
        aRow = (t < S_ST) ? (A  + ((long long)b * S_ST  + t)            * Dn)
                          : (A2 + ((long long)b * S_INP + (t - S_ST))   * Dn);
    } else {
        aRow = Ab + (long long)(m0 + arow) * lda;
    }
    const float* bTrow = Bb + (long long)(n0 + arow) * ldb;  // only used in BMODE_T

    float4 ra[2], rb[2];
    const int NT = K / BK;

#define GEMM_LOAD(K0_)                                                          \
    do {                                                                        \
        _Pragma("unroll")                                                       \
        for (int it = 0; it < 2; ++it)                                          \
            ra[it] = *(const float4*)(aRow + (K0_) + (it * 2 + akv) * 4);       \
        if (BMODE == BMODE_N) {                                                 \
            _Pragma("unroll")                                                   \
            for (int it = 0; it < 2; ++it)                                      \
                rb[it] = *(const float4*)(Bb + (long long)((K0_) + brow + it * 8) * ldb \
                                          + n0 + bcv * 4);                      \
        } else {                                                                \
            _Pragma("unroll")                                                   \
            for (int it = 0; it < 2; ++it)                                      \
                rb[it] = *(const float4*)(bTrow + (K0_) + (it * 2 + akv) * 4);  \
        }                                                                       \
    } while (0)

#define GEMM_STAGE(BUF_)                                                        \
    do {                                                                        \
        _Pragma("unroll")                                                       \
        for (int it = 0; it < 2; ++it) {                                        \
            const int kk = (it * 2 + akv) * 4;                                  \
            As[BUF_][kk + 0][arow] = f2tf(ra[it].x);                            \
            As[BUF_][kk + 1][arow] = f2tf(ra[it].y);                            \
            As[BUF_][kk + 2][arow] = f2tf(ra[it].z);                            \
            As[BUF_][kk + 3][arow] = f2tf(ra[it].w);                            \
        }                                                                       \
        if (BMODE == BMODE_N) {                                                 \
            _Pragma("unroll")                                                   \
            for (int it = 0; it < 2; ++it) {                                    \
                uint4 t4;                                                       \
                t4.x = f2tf(rb[it].x); t4.y = f2tf(rb[it].y);                   \
                t4.z = f2tf(rb[it].z); t4.w = f2tf(rb[it].w);                   \
                *(uint4*)&Bs[BUF_][brow + it * 8][bcv * 4] = t4;                \
            }                                                                   \
        } else {                                                                \
            _Pragma("unroll")                                                   \
            for (int it = 0; it < 2; ++it) {                                    \
                const int kk = (it * 2 + akv) * 4;                              \
                Bs[BUF_][kk + 0][arow] = f2tf(rb[it].x);                        \
                Bs[BUF_][kk + 1][arow] = f2tf(rb[it].y);                        \
                Bs[BUF_][kk + 2][arow] = f2tf(rb[it].z);                        \
                Bs[BUF_][kk + 3][arow] = f2tf(rb[it].w);                        \
            }                                                                   \
        }                                                                       \
    } while (0)

    float acc[4][4][4];
#pragma unroll
    for (int i = 0; i < 4; ++i)
#pragma unroll
        for (int j = 0; j < 4; ++j)
#pragma unroll
            for (int c = 0; c < 4; ++c) acc[i][j][c] = 0.0f;

    GEMM_LOAD(0);
    GEMM_STAGE(0);
    __syncthreads();

    for (int kt = 0; kt < NT; ++kt) {
        const int buf = kt & 1;
        if (kt + 1 < NT) GEMM_LOAD((kt + 1) * BK);

#pragma unroll
        for (int ks = 0; ks < 2; ++ks) {
            const int kb = ks * 8;
            unsigned af[4][4], bf[4][2];
#pragma unroll
            for (int i = 0; i < 4; ++i) {
                const int mr = wm * 64 + i * 16;
                af[i][0] = As[buf][kb + tig    ][mr + g];
                af[i][1] = As[buf][kb + tig    ][mr + g + 8];
                af[i][2] = As[buf][kb + tig + 4][mr + g];
                af[i][3] = As[buf][kb + tig + 4][mr + g + 8];
            }
#pragma unroll
            for (int j = 0; j < 4; ++j) {
                const int nc = wn * 32 + j * 8;
                bf[j][0] = Bs[buf][kb + tig    ][nc + g];
                bf[j][1] = Bs[buf][kb + tig + 4][nc + g];
            }
#pragma unroll
            for (int i = 0; i < 4; ++i)
#pragma unroll
                for (int j = 0; j < 4; ++j)
                    asm volatile(
                        "mma.sync.aligned.m16n8k8.row.col.f32.tf32.tf32.f32 "
                        "{%0,%1,%2,%3}, {%4,%5,%6,%7}, {%8,%9}, {%0,%1,%2,%3};\n"
                        : "+f"(acc[i][j][0]), "+f"(acc[i][j][1]),
                          "+f"(acc[i][j][2]), "+f"(acc[i][j][3])
                        : "r"(af[i][0]), "r"(af[i][1]), "r"(af[i][2]), "r"(af[i][3]),
                          "r"(bf[j][0]), "r"(bf[j][1]));
        }

        if (kt + 1 < NT) GEMM_STAGE((kt + 1) & 1);
        __syncthreads();
    }
#undef GEMM_LOAD
#undef GEMM_STAGE

    // epilogue
#pragma unroll
    for (int i = 0; i < 4; ++i) {
        const int r0 = m0 + wm * 64 + i * 16 + g;
#pragma unroll
        for (int j = 0; j < 4; ++j) {
            const int c0 = n0 + wn * 32 + j * 8 + tig * 2;
            float v0 = acc[i][j][0] * scale;
            float v1 = acc[i][j][1] * scale;
            float v2 = acc[i][j][2] * scale;
            float v3 = acc[i][j][3] * scale;
            if (biasb) {
                const float b0 = biasb[c0], b1 = biasb[c0 + 1];
                v0 += b0; v1 += b1; v2 += b0; v3 += b1;
            }
            if (RELU) {
                v0 = fmaxf(v0, 0.0f); v1 = fmaxf(v1, 0.0f);
                v2 = fmaxf(v2, 0.0f); v3 = fmaxf(v3, 0.0f);
            }
            *(float2*)(Cb + (long long)r0       * ldc + c0) = make_float2(v0, v1);
            *(float2*)(Cb + (long long)(r0 + 8) * ldc + c0) = make_float2(v2, v3);
        }
    }
}

// ---------------- softmax over rows of length 2048 --------------------------
__global__ void softmax2048(float* __restrict__ data)
{
    float* p = data + (long long)blockIdx.x * 2048;
    const int tid = threadIdx.x;
    const int lane = tid & 31, warp = tid >> 5;

    __shared__ float redA[8];
    __shared__ float redB[8];

    float v[8];
    float mx = -3.0e38f;
#pragma unroll
    for (int i = 0; i < 8; ++i) { v[i] = p[tid + i * 256]; mx = fmaxf(mx, v[i]); }
#pragma unroll
    for (int o = 16; o; o >>= 1) mx = fmaxf(mx, __shfl_xor_sync(0xffffffffu, mx, o));
    if (lane == 0) redA[warp] = mx;
    __syncthreads();
    if (tid < 32) {
        float m2 = (tid < 8) ? redA[tid] : -3.0e38f;
#pragma unroll
        for (int o = 4; o; o >>= 1) m2 = fmaxf(m2, __shfl_xor_sync(0xffffffffu, m2, o));
        if (tid == 0) redB[0] = m2;
    }
    __syncthreads();
    mx = redB[0];

    float s = 0.0f;
#pragma unroll
    for (int i = 0; i < 8; ++i) { v[i] = __expf(v[i] - mx); s += v[i]; }
#pragma unroll
    for (int o = 16; o; o >>= 1) s += __shfl_xor_sync(0xffffffffu, s, o);
    if (lane == 0) redA[warp] = s;
    __syncthreads();
    if (tid < 32) {
        float s2 = (tid < 8) ? redA[tid] : 0.0f;
#pragma unroll
        for (int o = 4; o; o >>= 1) s2 += __shfl_xor_sync(0xffffffffu, s2, o);
        if (tid == 0) redB[1] = s2;
    }
    __syncthreads();
    const float inv = 1.0f / redB[1];
#pragma unroll
    for (int i = 0; i < 8; ++i) p[tid + i * 256] = v[i] * inv;
}

// ---------------- out = LayerNorm(a + r) over D=1024 ------------------------
__global__ void add_ln1024(const float* __restrict__ a, const float* __restrict__ r,
                           const float* __restrict__ gw, const float* __restrict__ bw,
                           float* __restrict__ out)
{
    const long long base = (long long)blockIdx.x * 1024;
    const int tid = threadIdx.x;
    const int lane = tid & 31, warp = tid >> 5;

    __shared__ float rs[8], rq[8];
    __shared__ float fin[2];

    float v[4];
    float s = 0.0f, sq = 0.0f;
#pragma unroll
    for (int i = 0; i < 4; ++i) {
        const int c = tid + i * 256;
        const float x = a[base + c] + r[base + c];
        v[i] = x; s += x; sq += x * x;
    }
#pragma unroll
    for (int o = 16; o; o >>= 1) {
        s  += __shfl_xor_sync(0xffffffffu, s,  o);
        sq += __shfl_xor_sync(0xffffffffu, sq, o);
    }
    if (lane == 0) { rs[warp] = s; rq[warp] = sq; }
    __syncthreads();
    if (tid < 32) {
        float s2 = (tid < 8) ? rs[tid] : 0.0f;
        float q2 = (tid < 8) ? rq[tid] : 0.0f;
#pragma unroll
        for (int o = 4; o; o >>= 1) {
            s2 += __shfl_xor_sync(0xffffffffu, s2, o);
            q2 += __shfl_xor_sync(0xffffffffu, q2, o);
        }
        if (tid == 0) { fin[0] = s2; fin[1] = q2; }
    }
    __syncthreads();
    const float mean = fin[0] * (1.0f / 1024.0f);
    float var = fin[1] * (1.0f / 1024.0f) - mean * mean;
    var = fmaxf(var, 0.0f);
    const float inv = rsqrtf(var + 1e-6f);
#pragma unroll
    for (int i = 0; i < 4; ++i) {
        const int c = tid + i * 256;
        out[base + c] = (v[i] - mean) * inv * gw[c] + bw[c];
    }
}

// ---------------- gated = relu(g1) * g2 (in place into g1) ------------------
__global__ void gated_mul(float* __restrict__ a, const float* __restrict__ b)
{
    const long long i = ((long long)blockIdx.x * 256 + threadIdx.x) * 4;
    float4 x = *(const float4*)(a + i);
    const float4 y = *(const float4*)(b + i);
    x.x = fmaxf(x.x, 0.0f) * y.x;
    x.y = fmaxf(x.y, 0.0f) * y.y;
    x.z = fmaxf(x.z, 0.0f) * y.z;
    x.w = fmaxf(x.w, 0.0f) * y.w;
    *(float4*)(a + i) = x;
}

} // namespace stb

// ---------------------------------------------------------------------------
extern "C" void kernel_launch(void* const* d_in, const int* in_sizes, int n_in,
                              void* d_out, int out_size)
{
    using namespace stb;
    (void)in_sizes; (void)n_in; (void)out_size;

    const float* state = (const float*)d_in[0];
    const float* input = (const float*)d_in[1];
    const float* Wk    = (const float*)d_in[2];
    const float* bk    = (const float*)d_in[3];
    const float* Wv    = (const float*)d_in[4];
    const float* bv    = (const float*)d_in[5];
    const float* Wq    = (const float*)d_in[6];
    const float* bq    = (const float*)d_in[7];
    const float* Wo    = (const float*)d_in[8];
    const float* bo    = (const float*)d_in[9];
    const float* ln1g  = (const float*)d_in[10];
    const float* ln1b  = (const float*)d_in[11];
    const float* Wi    = (const float*)d_in[12];
    const float* bi    = (const float*)d_in[13];
    const float* Wg    = (const float*)d_in[14];
    const float* bg    = (const float*)d_in[15];
    const float* Wl    = (const float*)d_in[16];
    const float* bl    = (const float*)d_in[17];
    const float* Wf    = (const float*)d_in[18];
    const float* bf    = (const float*)d_in[19];
    const float* ln2g  = (const float*)d_in[20];
    const float* ln2b  = (const float*)d_in[21];
    float* out = (float*)d_out;

    float *pk, *pv, *pq, *ps, *pcat, *pt1, *px, *pin, *pg1, *pg2;
    cudaGetSymbolAddress((void**)&pk,   g_k);
    cudaGetSymbolAddress((void**)&pv,   g_v);
    cudaGetSymbolAddress((void**)&pq,   g_q);
    cudaGetSymbolAddress((void**)&ps,   g_s);
    cudaGetSymbolAddress((void**)&pcat, g_cat);
    cudaGetSymbolAddress((void**)&pt1,  g_t1);
    cudaGetSymbolAddress((void**)&px,   g_x);
    cudaGetSymbolAddress((void**)&pin,  g_in);
    cudaGetSymbolAddress((void**)&pg1,  g_g1);
    cudaGetSymbolAddress((void**)&pg2,  g_g2);

    const long long LL512x1024  = 512LL * 1024;
    const long long LL512x2048  = 512LL * 2048;
    const long long LL2048x1024 = 2048LL * 1024;

    // 1-2: k, v = concat(state,input) @ W + b   [8192,1024] = [8192,1024]x[1024,1024]
    gemm_tf32<AMODE_CONCAT, BMODE_N, false><<<dim3(8, 64, 1), 256>>>(
        state, input, Wk, bk, pk, 8192, 1024, 1024, 1024, 1024, 1024,
        1, 0, 0, 0, 0, 0, 0, 0, 1.0f);
    gemm_tf32<AMODE_CONCAT, BMODE_N, false><<<dim3(8, 64, 1), 256>>>(
        state, input, Wv, bv, pv, 8192, 1024, 1024, 1024, 1024, 1024,
        1, 0, 0, 0, 0, 0, 0, 0, 1.0f);

    // 3: q[b,h] = state[b] @ Wq[h] + bq[h]   (z = b*8+h, 32 slices)
    gemm_tf32<AMODE_DIRECT, BMODE_N, false><<<dim3(8, 4, 32), 256>>>(
        state, (const float*)0, Wq, bq, pq, 512, 1024, 1024, 1024, 1024, 1024,
        8, LL512x1024, 0, 0, 1024LL * 1024, 8 * LL512x1024, LL512x1024, 1024, 1.0f);

    // 4: scores[b,h] = q[b,h] @ k[b]^T / 32   (B operand K-contiguous)
    gemm_tf32<AMODE_DIRECT, BMODE_T, false><<<dim3(16, 4, 32), 256>>>(
        pq, (const float*)0, pk, (const float*)0, ps, 512, 2048, 1024, 1024, 1024, 2048,
        8, 8 * LL512x1024, LL512x1024, LL2048x1024, 0, 8 * LL512x2048, LL512x2048, 0,
        0.03125f);

    // 5: softmax over T
    softmax2048<<<4 * 8 * 512, 256>>>(ps);

    // 6: ctx[b,h] = attn[b,h] @ v[b]  -> written directly in concat layout [B,S,H*D]
    gemm_tf32<AMODE_DIRECT, BMODE_N, false><<<dim3(8, 4, 32), 256>>>(
        ps, (const float*)0, pv, (const float*)0, pcat, 512, 1024, 2048, 2048, 1024, 8192,
        8, 8 * LL512x2048, LL512x2048, LL2048x1024, 0, 512LL * 8192, 1024, 0, 1.0f);

    // 7: attn_out = concat @ Wo + bo   [2048,1024] = [2048,8192]x[8192,1024]
    gemm_tf32<AMODE_DIRECT, BMODE_N, false><<<dim3(8, 16, 1), 256>>>(
        pcat, (const float*)0, Wo, bo, pt1, 2048, 1024, 8192, 8192, 1024, 1024,
        1, 0, 0, 0, 0, 0, 0, 0, 1.0f);

    // 8: x = LN(attn_out + state)
    add_ln1024<<<2048, 256>>>(pt1, state, ln1g, ln1b, px);

    // 9: inner = relu(x @ Wi + bi)   [2048,4096]
    gemm_tf32<AMODE_DIRECT, BMODE_N, true><<<dim3(32, 16, 1), 256>>>(
        px, (const float*)0, Wi, bi, pin, 2048, 4096, 1024, 1024, 4096, 4096,
        1, 0, 0, 0, 0, 0, 0, 0, 1.0f);

    // 10-11: g1 = inner @ Wg + bg ; g2 = inner @ Wl + bl   [2048,4096]x[4096,4096]
    gemm_tf32<AMODE_DIRECT, BMODE_N, false><<<dim3(32, 16, 1), 256>>>(
        pin, (const float*)0, Wg, bg, pg1, 2048, 4096, 4096, 4096, 4096, 4096,
        1, 0, 0, 0, 0, 0, 0, 0, 1.0f);
    gemm_tf32<AMODE_DIRECT, BMODE_N, false><<<dim3(32, 16, 1), 256>>>(
        pin, (const float*)0, Wl, bl, pg2, 2048, 4096, 4096, 4096, 4096, 4096,
        1, 0, 0, 0, 0, 0, 0, 0, 1.0f);

    // 12: gated = relu(g1) * g2 (into g1)
    gated_mul<<<8192, 256>>>(pg1, pg2);

    // 13: ff = gated @ Wf + bf   [2048,1024]
    gemm_tf32<AMODE_DIRECT, BMODE_N, false><<<dim3(8, 16, 1), 256>>>(
        pg1, (const float*)0, Wf, bf, pt1, 2048, 1024, 4096, 4096, 1024, 1024,
        1, 0, 0, 0, 0, 0, 0, 0, 1.0f);

    // 14: out = LN(ff + x)
    add_ln1024<<<2048, 256>>>(pt1, px, ln2g, ln2b, out);
}

// round 6
// speedup vs baseline: 1.1422x; 1.1422x over previous
#include <cuda_runtime.h>

// ---------------------------------------------------------------------------
// StateTransformerBlock on GB300 — round 2 kernel (resubmit #4): tf32 mma.sync
// + ldmatrix fragment loads. B=4, S_STATE=512, S_IN=1536, T=2048, D=1024,
// H=8, F=4096. All fp32 I/O.
// ---------------------------------------------------------------------------

#define DEV_INLINE __device__ __forceinline__

namespace stb {

constexpr int Bn      = 4;
constexpr int S_ST    = 512;
constexpr int S_INP   = 1536;
constexpr int Tn      = 2048;   // S_ST + S_INP
constexpr int Dn      = 1024;
constexpr int Hn      = 8;
constexpr int Fn      = 4096;

// ---------------- scratch (device globals; no allocation allowed) ----------
__device__ __align__(128) float g_k  [Bn * Tn * Dn];
__device__ __align__(128) float g_v  [Bn * Tn * Dn];
__device__ __align__(128) float g_q  [Bn * Hn * S_ST * Dn];
__device__ __align__(128) float g_s  [(long long)Bn * Hn * S_ST * Tn];
__device__ __align__(128) float g_cat[Bn * S_ST * Hn * Dn];
__device__ __align__(128) float g_t1 [Bn * S_ST * Dn];
__device__ __align__(128) float g_x  [Bn * S_ST * Dn];
__device__ __align__(128) float g_in [Bn * S_ST * Fn];
__device__ __align__(128) float g_g1 [Bn * S_ST * Fn];
__device__ __align__(128) float g_g2 [Bn * S_ST * Fn];

// ---------------- GEMM config ----------------------------------------------
constexpr int BM = 128, BN = 128, BK = 16;
constexpr int LDMK  = BK + 4;      // 20 words: ldmatrix rows hit distinct 16B groups
constexpr int LDB_S = BN + 8;      // 136 words: scalar B-frag LDS conflict-free

enum { AMODE_DIRECT = 0, AMODE_CONCAT = 1 };
enum { BMODE_N = 0, BMODE_T = 1 };    // N: B[k][n] n-contig;  T: B[n][k] k-contig

DEV_INLINE unsigned f2tf(float x) {
    unsigned r;
    asm("cvt.rna.tf32.f32 %0, %1;" : "=r"(r) : "f"(x));
    return r;
}

DEV_INLINE void ldsm_x4(unsigned& r0, unsigned& r1, unsigned& r2, unsigned& r3,
                        unsigned addr) {
    asm volatile("ldmatrix.sync.aligned.m8n8.x4.shared.b16 {%0,%1,%2,%3}, [%4];"
                 : "=r"(r0), "=r"(r1), "=r"(r2), "=r"(r3) : "r"(addr));
}

// A row-major [M,K] (or CONCAT-gathered rows of length 1024).
// BMODE_N: B row-major [K,N]. BMODE_T: element (k,n) at B[n*ldb + k].
// C row-major [M,N]. Batched over blockIdx.z: z -> (zb = z/ZH, zh = z%ZH).
template <int AM, int BMODE, bool RELU>
__global__ void __launch_bounds__(256, 2)
gemm_tf32(const float* __restrict__ A, const float* __restrict__ A2,
          const float* __restrict__ Bmat, const float* __restrict__ bias,
          float* __restrict__ C,
          int M, int N, int K, int lda, int ldb, int ldc, int ZH,
          long long aSB, long long aSH, long long bSB, long long bSH,
          long long cSB, long long cSH, long long biasSH, float scale)
{
    // A staged [m][k], k-contiguous, stride LDMK
    __shared__ __align__(16) unsigned As[2][BM][LDMK];
    constexpr int BS_ROWS = (BMODE == BMODE_T) ? BN : BK;
    constexpr int BS_LD   = (BMODE == BMODE_T) ? LDMK : LDB_S;
    __shared__ __align__(16) unsigned Bs[2][BS_ROWS][BS_LD];

    constexpr unsigned A_BUF = BM * LDMK * 4;       // bytes per A buffer
    constexpr unsigned B_BUF = BS_ROWS * BS_LD * 4; // bytes per B buffer

    const int z  = blockIdx.z;
    const int zb = z / ZH, zh = z - zb * ZH;
    const float* Ab = A    + zb * aSB + zh * aSH;
    const float* Bb = Bmat + zb * bSB + zh * bSH;
    float*       Cb = C    + zb * cSB + zh * cSH;
    const float* biasb = bias ? (bias + zh * biasSH) : (const float*)0;

    const int m0 = blockIdx.y * BM;
    const int n0 = blockIdx.x * BN;
    const int tid  = threadIdx.x;
    const int lane = tid & 31;
    const int warp = tid >> 5;
    const int wm = warp & 1;          // 2 warps along M (64 rows each)
    const int wn = warp >> 1;         // 4 warps along N (32 cols each)
    const int g   = lane >> 2;        // groupID 0..7
    const int tig = lane & 3;         // threadInGroup 0..3

    // staging maps
    const int srow = tid & 127;       // A (and B-T) staged row
    const int skh  = tid >> 7;        // which 8-k half
    const int bcv  = tid & 31;        // B(N) float4 column
    const int brow = tid >> 5;        // B(N) k-row 0..7

    // A row base pointer (constant across the k loop)
    const float* aRow;
    if (AM == AMODE_CONCAT) {
        const int m = m0 + srow;
        const int b = m >> 11;        // / 2048
        const int t = m & 2047;
        aRow = (t < S_ST) ? (A  + ((long long)b * S_ST  + t)          * Dn)
                          : (A2 + ((long long)b * S_INP + (t - S_ST)) * Dn);
    } else {
        aRow = Ab + (long long)(m0 + srow) * lda;
    }
    const float* bTrow = Bb + (long long)(n0 + srow) * ldb;  // BMODE_T only

    // ldmatrix per-thread fragment offsets
    const unsigned aBase = (unsigned)__cvta_generic_to_shared(&As[0][0][0]);
    const unsigned bBase = (unsigned)__cvta_generic_to_shared(&Bs[0][0][0]);
    // A: row = wm*64 + i*16 + (lane&15), col = ks*8 + (lane>>4)*4
    const unsigned aOff = ((wm * 64 + (lane & 15)) * LDMK + (lane >> 4) * 4) * 4;
    // B(T): row n = wn*32 + jp*16 + (lane&7) + (lane>>4)*8, col = ks*8 + ((lane>>3)&1)*4
    const unsigned bOff = ((wn * 32 + (lane & 7) + (lane >> 4) * 8) * LDMK
                           + ((lane >> 3) & 1) * 4) * 4;

    float4 ra[2], rb[2];
    const int NT = K / BK;

#define GEMM_LOAD(K0_)                                                          \
    do {                                                                        \
        ra[0] = *(const float4*)(aRow + (K0_) + skh * 8);                       \
        ra[1] = *(const float4*)(aRow + (K0_) + skh * 8 + 4);                   \
        if (BMODE == BMODE_N) {                                                 \
            _Pragma("unroll")                                                   \
            for (int it = 0; it < 2; ++it)                                      \
                rb[it] = *(const float4*)(Bb + (long long)((K0_) + brow + it * 8) * ldb \
                                          + n0 + bcv * 4);                      \
        } else {                                                                \
            rb[0] = *(const float4*)(bTrow + (K0_) + skh * 8);                  \
            rb[1] = *(const float4*)(bTrow + (K0_) + skh * 8 + 4);              \
        }                                                                       \
    } while (0)

#define GEMM_STAGE(BUF_)                                                        \
    do {                                                                        \
        uint4 ua0, ua1;                                                         \
        ua0.x = f2tf(ra[0].x); ua0.y = f2tf(ra[0].y);                           \
        ua0.z = f2tf(ra[0].z); ua0.w = f2tf(ra[0].w);                           \
        ua1.x = f2tf(ra[1].x); ua1.y = f2tf(ra[1].y);                           \
        ua1.z = f2tf(ra[1].z); ua1.w = f2tf(ra[1].w);                           \
        *(uint4*)&As[BUF_][srow][skh * 8]     = ua0;                            \
        *(uint4*)&As[BUF_][srow][skh * 8 + 4] = ua1;                            \
        if (BMODE == BMODE_N) {                                                 \
            _Pragma("unroll")                                                   \
            for (int it = 0; it < 2; ++it) {                                    \
                uint4 t4;                                                       \
                t4.x = f2tf(rb[it].x); t4.y = f2tf(rb[it].y);                   \
                t4.z = f2tf(rb[it].z); t4.w = f2tf(rb[it].w);                   \
                *(uint4*)&Bs[BUF_][brow + it * 8][bcv * 4] = t4;                \
            }                                                                   \
        } else {                                                                \
            uint4 ub0, ub1;                                                     \
            ub0.x = f2tf(rb[0].x); ub0.y = f2tf(rb[0].y);                       \
            ub0.z = f2tf(rb[0].z); ub0.w = f2tf(rb[0].w);                       \
            ub1.x = f2tf(rb[1].x); ub1.y = f2tf(rb[1].y);                       \
            ub1.z = f2tf(rb[1].z); ub1.w = f2tf(rb[1].w);                       \
            *(uint4*)&Bs[BUF_][srow][skh * 8]     = ub0;                        \
            *(uint4*)&Bs[BUF_][srow][skh * 8 + 4] = ub1;                        \
        }                                                                       \
    } while (0)

    float acc[4][4][4];
#pragma unroll
    for (int i = 0; i < 4; ++i)
#pragma unroll
        for (int j = 0; j < 4; ++j)
#pragma unroll
            for (int c = 0; c < 4; ++c) acc[i][j][c] = 0.0f;

    GEMM_LOAD(0);
    GEMM_STAGE(0);
    __syncthreads();

    for (int kt = 0; kt < NT; ++kt) {
        const int buf = kt & 1;
        if (kt + 1 < NT) GEMM_LOAD((kt + 1) * BK);

#pragma unroll
        for (int ks = 0; ks < 2; ++ks) {
            const int kb = ks * 8;
            unsigned af[4][4], bf[4][2];
            // A fragments via ldmatrix.x4 (one per 16-row m tile)
#pragma unroll
            for (int i = 0; i < 4; ++i) {
                const unsigned addr = aBase + (unsigned)buf * A_BUF + aOff
                                    + (unsigned)i * (16 * LDMK * 4)
                                    + (unsigned)ks * 32;
                ldsm_x4(af[i][0], af[i][1], af[i][2], af[i][3], addr);
            }
            if (BMODE == BMODE_T) {
                // B fragments via ldmatrix.x4 (two n-tiles per load)
#pragma unroll
                for (int jp = 0; jp < 2; ++jp) {
                    const unsigned addr = bBase + (unsigned)buf * B_BUF + bOff
                                        + (unsigned)jp * (16 * LDMK * 4)
                                        + (unsigned)ks * 32;
                    ldsm_x4(bf[2 * jp][0], bf[2 * jp][1],
                            bf[2 * jp + 1][0], bf[2 * jp + 1][1], addr);
                }
            } else {
#pragma unroll
                for (int j = 0; j < 4; ++j) {
                    const int nc = wn * 32 + j * 8;
                    bf[j][0] = Bs[buf][kb + tig    ][nc + g];
                    bf[j][1] = Bs[buf][kb + tig + 4][nc + g];
                }
            }
#pragma unroll
            for (int i = 0; i < 4; ++i)
#pragma unroll
                for (int j = 0; j < 4; ++j)
                    asm volatile(
                        "mma.sync.aligned.m16n8k8.row.col.f32.tf32.tf32.f32 "
                        "{%0,%1,%2,%3}, {%4,%5,%6,%7}, {%8,%9}, {%0,%1,%2,%3};\n"
                        : "+f"(acc[i][j][0]), "+f"(acc[i][j][1]),
                          "+f"(acc[i][j][2]), "+f"(acc[i][j][3])
                        : "r"(af[i][0]), "r"(af[i][1]), "r"(af[i][2]), "r"(af[i][3]),
                          "r"(bf[j][0]), "r"(bf[j][1]));
        }

        if (kt + 1 < NT) GEMM_STAGE((kt + 1) & 1);
        __syncthreads();
    }
#undef GEMM_LOAD
#undef GEMM_STAGE

    // epilogue
#pragma unroll
    for (int i = 0; i < 4; ++i) {
        const int r0 = m0 + wm * 64 + i * 16 + g;
#pragma unroll
        for (int j = 0; j < 4; ++j) {
            const int c0 = n0 + wn * 32 + j * 8 + tig * 2;
            float v0 = acc[i][j][0] * scale;
            float v1 = acc[i][j][1] * scale;
            float v2 = acc[i][j][2] * scale;
            float v3 = acc[i][j][3] * scale;
            if (biasb) {
                const float b0 = biasb[c0], b1 = biasb[c0 + 1];
                v0 += b0; v1 += b1; v2 += b0; v3 += b1;
            }
            if (RELU) {
                v0 = fmaxf(v0, 0.0f); v1 = fmaxf(v1, 0.0f);
                v2 = fmaxf(v2, 0.0f); v3 = fmaxf(v3, 0.0f);
            }
            *(float2*)(Cb + (long long)r0       * ldc + c0) = make_float2(v0, v1);
            *(float2*)(Cb + (long long)(r0 + 8) * ldc + c0) = make_float2(v2, v3);
        }
    }
}

// ---------------- softmax over rows of length 2048 --------------------------
__global__ void softmax2048(float* __restrict__ data)
{
    float* p = data + (long long)blockIdx.x * 2048;
    const int tid = threadIdx.x;
    const int lane = tid & 31, warp = tid >> 5;

    __shared__ float redA[8];
    __shared__ float redB[8];

    float v[8];
    float mx = -3.0e38f;
#pragma unroll
    for (int i = 0; i < 8; ++i) { v[i] = p[tid + i * 256]; mx = fmaxf(mx, v[i]); }
#pragma unroll
    for (int o = 16; o; o >>= 1) mx = fmaxf(mx, __shfl_xor_sync(0xffffffffu, mx, o));
    if (lane == 0) redA[warp] = mx;
    __syncthreads();
    if (tid < 32) {
        float m2 = (tid < 8) ? redA[tid] : -3.0e38f;
#pragma unroll
        for (int o = 4; o; o >>= 1) m2 = fmaxf(m2, __shfl_xor_sync(0xffffffffu, m2, o));
        if (tid == 0) redB[0] = m2;
    }
    __syncthreads();
    mx = redB[0];

    float s = 0.0f;
#pragma unroll
    for (int i = 0; i < 8; ++i) { v[i] = __expf(v[i] - mx); s += v[i]; }
#pragma unroll
    for (int o = 16; o; o >>= 1) s += __shfl_xor_sync(0xffffffffu, s, o);
    if (lane == 0) redA[warp] = s;
    __syncthreads();
    if (tid < 32) {
        float s2 = (tid < 8) ? redA[tid] : 0.0f;
#pragma unroll
        for (int o = 4; o; o >>= 1) s2 += __shfl_xor_sync(0xffffffffu, s2, o);
        if (tid == 0) redB[1] = s2;
    }
    __syncthreads();
    const float inv = 1.0f / redB[1];
#pragma unroll
    for (int i = 0; i < 8; ++i) p[tid + i * 256] = v[i] * inv;
}

// ---------------- out = LayerNorm(a + r) over D=1024 ------------------------
__global__ void add_ln1024(const float* __restrict__ a, const float* __restrict__ r,
                           const float* __restrict__ gw, const float* __restrict__ bw,
                           float* __restrict__ out)
{
    const long long base = (long long)blockIdx.x * 1024;
    const int tid = threadIdx.x;
    const int lane = tid & 31, warp = tid >> 5;

    __shared__ float rs[8], rq[8];
    __shared__ float fin[2];

    float v[4];
    float s = 0.0f, sq = 0.0f;
#pragma unroll
    for (int i = 0; i < 4; ++i) {
        const int c = tid + i * 256;
        const float x = a[base + c] + r[base + c];
        v[i] = x; s += x; sq += x * x;
    }
#pragma unroll
    for (int o = 16; o; o >>= 1) {
        s  += __shfl_xor_sync(0xffffffffu, s,  o);
        sq += __shfl_xor_sync(0xffffffffu, sq, o);
    }
    if (lane == 0) { rs[warp] = s; rq[warp] = sq; }
    __syncthreads();
    if (tid < 32) {
        float s2 = (tid < 8) ? rs[tid] : 0.0f;
        float q2 = (tid < 8) ? rq[tid] : 0.0f;
#pragma unroll
        for (int o = 4; o; o >>= 1) {
            s2 += __shfl_xor_sync(0xffffffffu, s2, o);
            q2 += __shfl_xor_sync(0xffffffffu, q2, o);
        }
        if (tid == 0) { fin[0] = s2; fin[1] = q2; }
    }
    __syncthreads();
    const float mean = fin[0] * (1.0f / 1024.0f);
    float var = fin[1] * (1.0f / 1024.0f) - mean * mean;
    var = fmaxf(var, 0.0f);
    const float inv = rsqrtf(var + 1e-6f);
#pragma unroll
    for (int i = 0; i < 4; ++i) {
        const int c = tid + i * 256;
        out[base + c] = (v[i] - mean) * inv * gw[c] + bw[c];
    }
}

// ---------------- gated = relu(g1) * g2 (in place into g1) ------------------
__global__ void gated_mul(float* __restrict__ a, const float* __restrict__ b)
{
    const long long i = ((long long)blockIdx.x * 256 + threadIdx.x) * 4;
    float4 x = *(const float4*)(a + i);
    const float4 y = *(const float4*)(b + i);
    x.x = fmaxf(x.x, 0.0f) * y.x;
    x.y = fmaxf(x.y, 0.0f) * y.y;
    x.z = fmaxf(x.z, 0.0f) * y.z;
    x.w = fmaxf(x.w, 0.0f) * y.w;
    *(float4*)(a + i) = x;
}

} // namespace stb

// ---------------------------------------------------------------------------
extern "C" void kernel_launch(void* const* d_in, const int* in_sizes, int n_in,
                              void* d_out, int out_size)
{
    using namespace stb;
    (void)in_sizes; (void)n_in; (void)out_size;

    const float* state = (const float*)d_in[0];
    const float* input = (const float*)d_in[1];
    const float* Wk    = (const float*)d_in[2];
    const float* bk    = (const float*)d_in[3];
    const float* Wv    = (const float*)d_in[4];
    const float* bv    = (const float*)d_in[5];
    const float* Wq    = (const float*)d_in[6];
    const float* bq    = (const float*)d_in[7];
    const float* Wo    = (const float*)d_in[8];
    const float* bo    = (const float*)d_in[9];
    const float* ln1g  = (const float*)d_in[10];
    const float* ln1b  = (const float*)d_in[11];
    const float* Wi    = (const float*)d_in[12];
    const float* bi    = (const float*)d_in[13];
    const float* Wg    = (const float*)d_in[14];
    const float* bg    = (const float*)d_in[15];
    const float* Wl    = (const float*)d_in[16];
    const float* bl    = (const float*)d_in[17];
    const float* Wf    = (const float*)d_in[18];
    const float* bf    = (const float*)d_in[19];
    const float* ln2g  = (const float*)d_in[20];
    const float* ln2b  = (const float*)d_in[21];
    float* out = (float*)d_out;

    float *pk, *pv, *pq, *ps, *pcat, *pt1, *px, *pin, *pg1, *pg2;
    cudaGetSymbolAddress((void**)&pk,   g_k);
    cudaGetSymbolAddress((void**)&pv,   g_v);
    cudaGetSymbolAddress((void**)&pq,   g_q);
    cudaGetSymbolAddress((void**)&ps,   g_s);
    cudaGetSymbolAddress((void**)&pcat, g_cat);
    cudaGetSymbolAddress((void**)&pt1,  g_t1);
    cudaGetSymbolAddress((void**)&px,   g_x);
    cudaGetSymbolAddress((void**)&pin,  g_in);
    cudaGetSymbolAddress((void**)&pg1,  g_g1);
    cudaGetSymbolAddress((void**)&pg2,  g_g2);

    const long long LL512x1024  = 512LL * 1024;
    const long long LL512x2048  = 512LL * 2048;
    const long long LL2048x1024 = 2048LL * 1024;

    // 1-2: k, v = concat(state,input) @ W + b   [8192,1024]
    gemm_tf32<AMODE_CONCAT, BMODE_N, false><<<dim3(8, 64, 1), 256>>>(
        state, input, Wk, bk, pk, 8192, 1024, 1024, 1024, 1024, 1024,
        1, 0, 0, 0, 0, 0, 0, 0, 1.0f);
    gemm_tf32<AMODE_CONCAT, BMODE_N, false><<<dim3(8, 64, 1), 256>>>(
        state, input, Wv, bv, pv, 8192, 1024, 1024, 1024, 1024, 1024,
        1, 0, 0, 0, 0, 0, 0, 0, 1.0f);

    // 3: q[b,h] = state[b] @ Wq[h] + bq[h]   (z = b*8+h)
    gemm_tf32<AMODE_DIRECT, BMODE_N, false><<<dim3(8, 4, 32), 256>>>(
        state, (const float*)0, Wq, bq, pq, 512, 1024, 1024, 1024, 1024, 1024,
        8, LL512x1024, 0, 0, 1024LL * 1024, 8 * LL512x1024, LL512x1024, 1024, 1.0f);

    // 4: scores[b,h] = q[b,h] @ k[b]^T / 32   (B K-contiguous -> ldmatrix path)
    gemm_tf32<AMODE_DIRECT, BMODE_T, false><<<dim3(16, 4, 32), 256>>>(
        pq, (const float*)0, pk, (const float*)0, ps, 512, 2048, 1024, 1024, 1024, 2048,
        8, 8 * LL512x1024, LL512x1024, LL2048x1024, 0, 8 * LL512x2048, LL512x2048, 0,
        0.03125f);

    // 5: softmax over T
    softmax2048<<<4 * 8 * 512, 256>>>(ps);

    // 6: ctx[b,h] = attn[b,h] @ v[b]  -> written directly in concat layout [B,S,H*D]
    gemm_tf32<AMODE_DIRECT, BMODE_N, false><<<dim3(8, 4, 32), 256>>>(
        ps, (const float*)0, pv, (const float*)0, pcat, 512, 1024, 2048, 2048, 1024, 8192,
        8, 8 * LL512x2048, LL512x2048, LL2048x1024, 0, 512LL * 8192, 1024, 0, 1.0f);

    // 7: attn_out = concat @ Wo + bo   [2048,1024]
    gemm_tf32<AMODE_DIRECT, BMODE_N, false><<<dim3(8, 16, 1), 256>>>(
        pcat, (const float*)0, Wo, bo, pt1, 2048, 1024, 8192, 8192, 1024, 1024,
        1, 0, 0, 0, 0, 0, 0, 0, 1.0f);

    // 8: x = LN(attn_out + state)
    add_ln1024<<<2048, 256>>>(pt1, state, ln1g, ln1b, px);

    // 9: inner = relu(x @ Wi + bi)   [2048,4096]
    gemm_tf32<AMODE_DIRECT, BMODE_N, true><<<dim3(32, 16, 1), 256>>>(
        px, (const float*)0, Wi, bi, pin, 2048, 4096, 1024, 1024, 4096, 4096,
        1, 0, 0, 0, 0, 0, 0, 0, 1.0f);

    // 10-11: g1 = inner @ Wg + bg ; g2 = inner @ Wl + bl
    gemm_tf32<AMODE_DIRECT, BMODE_N, false><<<dim3(32, 16, 1), 256>>>(
        pin, (const float*)0, Wg, bg, pg1, 2048, 4096, 4096, 4096, 4096, 4096,
        1, 0, 0, 0, 0, 0, 0, 0, 1.0f);
    gemm_tf32<AMODE_DIRECT, BMODE_N, false><<<dim3(32, 16, 1), 256>>>(
        pin, (const float*)0, Wl, bl, pg2, 2048, 4096, 4096, 4096, 4096, 4096,
        1, 0, 0, 0, 0, 0, 0, 0, 1.0f);

    // 12: gated = relu(g1) * g2 (into g1)
    gated_mul<<<8192, 256>>>(pg1, pg2);

    // 13: ff = gated @ Wf + bf   [2048,1024]
    gemm_tf32<AMODE_DIRECT, BMODE_N, false><<<dim3(8, 16, 1), 256>>>(
        pg1, (const float*)0, Wf, bf, pt1, 2048, 1024, 4096, 4096, 1024, 1024,
        1, 0, 0, 0, 0, 0, 0, 0, 1.0f);

    // 14: out = LN(ff + x)
    add_ln1024<<<2048, 256>>>(pt1, px, ln2g, ln2b, out);
}

// round 12
// speedup vs baseline: 1.2589x; 1.1022x over previous
#include <cuda_runtime.h>

// ---------------------------------------------------------------------------
// StateTransformerBlock on GB300 — round 7 kernel (resubmit #5): tf32 mma.sync
// + ldmatrix + 3-stage cp.async pipeline, consumer-side tf32 conversion.
// B=4, S_STATE=512, S_IN=1536, T=2048, D=1024, H=8, F=4096. All fp32 I/O.
// ---------------------------------------------------------------------------

#define DEV_INLINE __device__ __forceinline__

namespace stb {

constexpr int Bn      = 4;
constexpr int S_ST    = 512;
constexpr int S_INP   = 1536;
constexpr int Tn      = 2048;   // S_ST + S_INP
constexpr int Dn      = 1024;
constexpr int Hn      = 8;
constexpr int Fn      = 4096;

// ---------------- scratch (device globals; no allocation allowed) ----------
__device__ __align__(128) float g_k  [Bn * Tn * Dn];
__device__ __align__(128) float g_v  [Bn * Tn * Dn];
__device__ __align__(128) float g_q  [Bn * Hn * S_ST * Dn];
__device__ __align__(128) float g_s  [(long long)Bn * Hn * S_ST * Tn];
__device__ __align__(128) float g_cat[Bn * S_ST * Hn * Dn];
__device__ __align__(128) float g_t1 [Bn * S_ST * Dn];
__device__ __align__(128) float g_x  [Bn * S_ST * Dn];
__device__ __align__(128) float g_in [Bn * S_ST * Fn];
__device__ __align__(128) float g_g1 [Bn * S_ST * Fn];
__device__ __align__(128) float g_g2 [Bn * S_ST * Fn];

// ---------------- GEMM config ----------------------------------------------
constexpr int BM = 128, BN = 128, BK = 16;
constexpr int STAGES = 3;
constexpr int LDMK  = BK + 4;      // 20 words: ldmatrix rows hit distinct 16B groups
constexpr int LDB_S = BN + 8;      // 136 words: scalar B-frag LDS conflict-free

enum { AMODE_DIRECT = 0, AMODE_CONCAT = 1 };
enum { BMODE_N = 0, BMODE_T = 1 };    // N: B[k][n] n-contig;  T: B[n][k] k-contig

DEV_INLINE unsigned f2tfu(unsigned x) {
    unsigned r;
    asm("cvt.rna.tf32.f32 %0, %1;" : "=r"(r) : "f"(__uint_as_float(x)));
    return r;
}

DEV_INLINE void ldsm_x4(unsigned& r0, unsigned& r1, unsigned& r2, unsigned& r3,
                        unsigned addr) {
    asm volatile("ldmatrix.sync.aligned.m8n8.x4.shared.b16 {%0,%1,%2,%3}, [%4];"
                 : "=r"(r0), "=r"(r1), "=r"(r2), "=r"(r3) : "r"(addr));
}

#define CP_ASYNC16(DST_, SRC_) \
    asm volatile("cp.async.cg.shared.global [%0], [%1], 16;" :: "r"(DST_), "l"(SRC_))
#define CP_COMMIT() asm volatile("cp.async.commit_group;")
#define CP_WAIT(N_) asm volatile("cp.async.wait_group %0;" :: "n"(N_))

// smem bytes per instantiation (host + device)
constexpr int A_BUF_B   = BM * LDMK * 4;           // 10240
constexpr int B_BUF_T_B = BN * LDMK * 4;           // 10240
constexpr int B_BUF_N_B = BK * LDB_S * 4;          // 8704
constexpr int SMEM_T_BYTES = STAGES * (A_BUF_B + B_BUF_T_B);   // 61440
constexpr int SMEM_N_BYTES = STAGES * (A_BUF_B + B_BUF_N_B);   // 56832

// A row-major [M,K] (or CONCAT-gathered rows of length 1024).
// BMODE_N: B row-major [K,N]. BMODE_T: element (k,n) at B[n*ldb + k].
// C row-major [M,N]. Batched over blockIdx.z: z -> (zb = z/ZH, zh = z%ZH).
template <int AM, int BMODE, bool RELU>
__global__ void __launch_bounds__(256, 2)
gemm_tf32(const float* __restrict__ A, const float* __restrict__ A2,
          const float* __restrict__ Bmat, const float* __restrict__ bias,
          float* __restrict__ C,
          int M, int N, int K, int lda, int ldb, int ldc, int ZH,
          long long aSB, long long aSH, long long bSB, long long bSH,
          long long cSB, long long cSH, long long biasSH, float scale)
{
    extern __shared__ __align__(16) unsigned smem_u[];
    constexpr int BS_ROWS = (BMODE == BMODE_T) ? BN : BK;
    constexpr int BS_LD   = (BMODE == BMODE_T) ? LDMK : LDB_S;
    constexpr unsigned A_BUF = BM * LDMK * 4;       // bytes per A stage
    constexpr unsigned B_BUF = BS_ROWS * BS_LD * 4; // bytes per B stage

    unsigned* Asm = smem_u;                               // STAGES*BM*LDMK words
    unsigned* Bsm = smem_u + STAGES * BM * LDMK;          // STAGES*BS_ROWS*BS_LD

    const int z  = blockIdx.z;
    const int zb = z / ZH, zh = z - zb * ZH;
    const float* Ab = A    + zb * aSB + zh * aSH;
    const float* Bb = Bmat + zb * bSB + zh * bSH;
    float*       Cb = C    + zb * cSB + zh * cSH;
    const float* biasb = bias ? (bias + zh * biasSH) : (const float*)0;

    const int m0 = blockIdx.y * BM;
    const int n0 = blockIdx.x * BN;
    const int tid  = threadIdx.x;
    const int lane = tid & 31;
    const int warp = tid >> 5;
    const int wm = warp & 1;          // 2 warps along M (64 rows each)
    const int wn = warp >> 1;         // 4 warps along N (32 cols each)
    const int g   = lane >> 2;        // groupID 0..7
    const int tig = lane & 3;         // threadInGroup 0..3

    // staging maps
    const int srow = tid & 127;       // A (and B-T) staged row
    const int skh  = tid >> 7;        // which 8-k half
    const int bcv  = tid & 31;        // B(N) float4 column
    const int brow = tid >> 5;        // B(N) k-row 0..7

    // A row base pointer (constant across the k loop)
    const float* aRow;
    if (AM == AMODE_CONCAT) {
        const int m = m0 + srow;
        const int b = m >> 11;        // / 2048
        const int t = m & 2047;
        aRow = (t < S_ST) ? (A  + ((long long)b * S_ST  + t)          * Dn)
                          : (A2 + ((long long)b * S_INP + (t - S_ST)) * Dn);
    } else {
        aRow = Ab + (long long)(m0 + srow) * lda;
    }
    const float* bTrow = Bb + (long long)(n0 + srow) * ldb;  // BMODE_T only

    // shared-space base addresses
    const unsigned aSm = (unsigned)__cvta_generic_to_shared(Asm);
    const unsigned bSm = (unsigned)__cvta_generic_to_shared(Bsm);

    // per-thread staging destination offsets (within one stage)
    const unsigned aStOff  = (unsigned)(srow * LDMK + skh * 8) * 4;
    const unsigned bStOffT = aStOff;                                  // same map
    const unsigned bStOffN = (unsigned)(brow * BS_LD + bcv * 4) * 4;

    // ldmatrix per-thread fragment offsets (within one stage)
    // A: row = wm*64 + i*16 + (lane&15), col = ks*8 + (lane>>4)*4
    const unsigned aOff = ((wm * 64 + (lane & 15)) * LDMK + (lane >> 4) * 4) * 4;
    // B(T): row n = wn*32 + jp*16 + (lane&7) + (lane>>4)*8, col = ks*8 + ((lane>>3)&1)*4
    const unsigned bOff = ((wn * 32 + (lane & 7) + (lane >> 4) * 8) * LDMK
                           + ((lane >> 3) & 1) * 4) * 4;

    const int NT = K / BK;

#define GEMM_COPY(K0_, S_)                                                      \
    do {                                                                        \
        const unsigned a0 = aSm + (unsigned)(S_) * A_BUF + aStOff;              \
        CP_ASYNC16(a0,      aRow + (K0_) + skh * 8);                            \
        CP_ASYNC16(a0 + 16, aRow + (K0_) + skh * 8 + 4);                        \
        if (BMODE == BMODE_N) {                                                 \
            _Pragma("unroll")                                                   \
            for (int it = 0; it < 2; ++it)                                      \
                CP_ASYNC16(bSm + (unsigned)(S_) * B_BUF + bStOffN               \
                               + (unsigned)it * (8 * BS_LD * 4),                \
                           Bb + (long long)((K0_) + brow + it * 8) * ldb        \
                              + n0 + bcv * 4);                                  \
        } else {                                                                \
            const unsigned b0 = bSm + (unsigned)(S_) * B_BUF + bStOffT;         \
            CP_ASYNC16(b0,      bTrow + (K0_) + skh * 8);                       \
            CP_ASYNC16(b0 + 16, bTrow + (K0_) + skh * 8 + 4);                   \
        }                                                                       \
    } while (0)

    float acc[4][4][4];
#pragma unroll
    for (int i = 0; i < 4; ++i)
#pragma unroll
        for (int j = 0; j < 4; ++j)
#pragma unroll
            for (int c = 0; c < 4; ++c) acc[i][j][c] = 0.0f;

    // prefetch STAGES-1 stages
#pragma unroll
    for (int s = 0; s < STAGES - 1; ++s) {
        GEMM_COPY(s * BK, s);
        CP_COMMIT();
    }

    for (int kt = 0; kt < NT; ++kt) {
        CP_WAIT(STAGES - 2);          // stage kt's copy complete
        __syncthreads();              // all warps done with stage (kt+2)%3 reads

        const int nk = kt + STAGES - 1;
        if (nk < NT) GEMM_COPY(nk * BK, nk % STAGES);
        CP_COMMIT();                  // commit (possibly empty) to keep counts aligned

        const int buf = kt % STAGES;
        const unsigned aStage = aSm + (unsigned)buf * A_BUF;
        const unsigned bStage = bSm + (unsigned)buf * B_BUF;

#pragma unroll
        for (int ks = 0; ks < 2; ++ks) {
            const int kb = ks * 8;
            unsigned af[4][4], bf[4][2];
            // A fragments via ldmatrix.x4 (one per 16-row m tile), then cvt
#pragma unroll
            for (int i = 0; i < 4; ++i) {
                const unsigned addr = aStage + aOff
                                    + (unsigned)i * (16 * LDMK * 4)
                                    + (unsigned)ks * 32;
                ldsm_x4(af[i][0], af[i][1], af[i][2], af[i][3], addr);
#pragma unroll
                for (int r = 0; r < 4; ++r) af[i][r] = f2tfu(af[i][r]);
            }
            if (BMODE == BMODE_T) {
#pragma unroll
                for (int jp = 0; jp < 2; ++jp) {
                    const unsigned addr = bStage + bOff
                                        + (unsigned)jp * (16 * LDMK * 4)
                                        + (unsigned)ks * 32;
                    ldsm_x4(bf[2 * jp][0], bf[2 * jp][1],
                            bf[2 * jp + 1][0], bf[2 * jp + 1][1], addr);
                }
#pragma unroll
                for (int j = 0; j < 4; ++j) {
                    bf[j][0] = f2tfu(bf[j][0]);
                    bf[j][1] = f2tfu(bf[j][1]);
                }
            } else {
#pragma unroll
                for (int j = 0; j < 4; ++j) {
                    const int nc = wn * 32 + j * 8;
                    bf[j][0] = f2tfu(Bsm[(buf * BS_ROWS + kb + tig    ) * BS_LD + nc + g]);
                    bf[j][1] = f2tfu(Bsm[(buf * BS_ROWS + kb + tig + 4) * BS_LD + nc + g]);
                }
            }
#pragma unroll
            for (int i = 0; i < 4; ++i)
#pragma unroll
                for (int j = 0; j < 4; ++j)
                    asm volatile(
                        "mma.sync.aligned.m16n8k8.row.col.f32.tf32.tf32.f32 "
                        "{%0,%1,%2,%3}, {%4,%5,%6,%7}, {%8,%9}, {%0,%1,%2,%3};\n"
                        : "+f"(acc[i][j][0]), "+f"(acc[i][j][1]),
                          "+f"(acc[i][j][2]), "+f"(acc[i][j][3])
                        : "r"(af[i][0]), "r"(af[i][1]), "r"(af[i][2]), "r"(af[i][3]),
                          "r"(bf[j][0]), "r"(bf[j][1]));
        }
    }
#undef GEMM_COPY

    // epilogue
#pragma unroll
    for (int i = 0; i < 4; ++i) {
        const int r0 = m0 + wm * 64 + i * 16 + g;
#pragma unroll
        for (int j = 0; j < 4; ++j) {
            const int c0 = n0 + wn * 32 + j * 8 + tig * 2;
            float v0 = acc[i][j][0] * scale;
            float v1 = acc[i][j][1] * scale;
            float v2 = acc[i][j][2] * scale;
            float v3 = acc[i][j][3] * scale;
            if (biasb) {
                const float b0 = biasb[c0], b1 = biasb[c0 + 1];
                v0 += b0; v1 += b1; v2 += b0; v3 += b1;
            }
            if (RELU) {
                v0 = fmaxf(v0, 0.0f); v1 = fmaxf(v1, 0.0f);
                v2 = fmaxf(v2, 0.0f); v3 = fmaxf(v3, 0.0f);
            }
            *(float2*)(Cb + (long long)r0       * ldc + c0) = make_float2(v0, v1);
            *(float2*)(Cb + (long long)(r0 + 8) * ldc + c0) = make_float2(v2, v3);
        }
    }
}

// ---------------- softmax over rows of length 2048 --------------------------
__global__ void softmax2048(float* __restrict__ data)
{
    float* p = data + (long long)blockIdx.x * 2048;
    const int tid = threadIdx.x;
    const int lane = tid & 31, warp = tid >> 5;

    __shared__ float redA[8];
    __shared__ float redB[8];

    float v[8];
    float mx = -3.0e38f;
#pragma unroll
    for (int i = 0; i < 8; ++i) { v[i] = p[tid + i * 256]; mx = fmaxf(mx, v[i]); }
#pragma unroll
    for (int o = 16; o; o >>= 1) mx = fmaxf(mx, __shfl_xor_sync(0xffffffffu, mx, o));
    if (lane == 0) redA[warp] = mx;
    __syncthreads();
    if (tid < 32) {
        float m2 = (tid < 8) ? redA[tid] : -3.0e38f;
#pragma unroll
        for (int o = 4; o; o >>= 1) m2 = fmaxf(m2, __shfl_xor_sync(0xffffffffu, m2, o));
        if (tid == 0) redB[0] = m2;
    }
    __syncthreads();
    mx = redB[0];

    float s = 0.0f;
#pragma unroll
    for (int i = 0; i < 8; ++i) { v[i] = __expf(v[i] - mx); s += v[i]; }
#pragma unroll
    for (int o = 16; o; o >>= 1) s += __shfl_xor_sync(0xffffffffu, s, o);
    if (lane == 0) redA[warp] = s;
    __syncthreads();
    if (tid < 32) {
        float s2 = (tid < 8) ? redA[tid] : 0.0f;
#pragma unroll
        for (int o = 4; o; o >>= 1) s2 += __shfl_xor_sync(0xffffffffu, s2, o);
        if (tid == 0) redB[1] = s2;
    }
    __syncthreads();
    const float inv = 1.0f / redB[1];
#pragma unroll
    for (int i = 0; i < 8; ++i) p[tid + i * 256] = v[i] * inv;
}

// ---------------- out = LayerNorm(a + r) over D=1024 ------------------------
__global__ void add_ln1024(const float* __restrict__ a, const float* __restrict__ r,
                           const float* __restrict__ gw, const float* __restrict__ bw,
                           float* __restrict__ out)
{
    const long long base = (long long)blockIdx.x * 1024;
    const int tid = threadIdx.x;
    const int lane = tid & 31, warp = tid >> 5;

    __shared__ float rs[8], rq[8];
    __shared__ float fin[2];

    float v[4];
    float s = 0.0f, sq = 0.0f;
#pragma unroll
    for (int i = 0; i < 4; ++i) {
        const int c = tid + i * 256;
        const float x = a[base + c] + r[base + c];
        v[i] = x; s += x; sq += x * x;
    }
#pragma unroll
    for (int o = 16; o; o >>= 1) {
        s  += __shfl_xor_sync(0xffffffffu, s,  o);
        sq += __shfl_xor_sync(0xffffffffu, sq, o);
    }
    if (lane == 0) { rs[warp] = s; rq[warp] = sq; }
    __syncthreads();
    if (tid < 32) {
        float s2 = (tid < 8) ? rs[tid] : 0.0f;
        float q2 = (tid < 8) ? rq[tid] : 0.0f;
#pragma unroll
        for (int o = 4; o; o >>= 1) {
            s2 += __shfl_xor_sync(0xffffffffu, s2, o);
            q2 += __shfl_xor_sync(0xffffffffu, q2, o);
        }
        if (tid == 0) { fin[0] = s2; fin[1] = q2; }
    }
    __syncthreads();
    const float mean = fin[0] * (1.0f / 1024.0f);
    float var = fin[1] * (1.0f / 1024.0f) - mean * mean;
    var = fmaxf(var, 0.0f);
    const float inv = rsqrtf(var + 1e-6f);
#pragma unroll
    for (int i = 0; i < 4; ++i) {
        const int c = tid + i * 256;
        out[base + c] = (v[i] - mean) * inv * gw[c] + bw[c];
    }
}

// ---------------- gated = relu(g1) * g2 (in place into g1) ------------------
__global__ void gated_mul(float* __restrict__ a, const float* __restrict__ b)
{
    const long long i = ((long long)blockIdx.x * 256 + threadIdx.x) * 4;
    float4 x = *(const float4*)(a + i);
    const float4 y = *(const float4*)(b + i);
    x.x = fmaxf(x.x, 0.0f) * y.x;
    x.y = fmaxf(x.y, 0.0f) * y.y;
    x.z = fmaxf(x.z, 0.0f) * y.z;
    x.w = fmaxf(x.w, 0.0f) * y.w;
    *(float4*)(a + i) = x;
}

} // namespace stb

// ---------------------------------------------------------------------------
extern "C" void kernel_launch(void* const* d_in, const int* in_sizes, int n_in,
                              void* d_out, int out_size)
{
    using namespace stb;
    (void)in_sizes; (void)n_in; (void)out_size;

    const float* state = (const float*)d_in[0];
    const float* input = (const float*)d_in[1];
    const float* Wk    = (const float*)d_in[2];
    const float* bk    = (const float*)d_in[3];
    const float* Wv    = (const float*)d_in[4];
    const float* bv    = (const float*)d_in[5];
    const float* Wq    = (const float*)d_in[6];
    const float* bq    = (const float*)d_in[7];
    const float* Wo    = (const float*)d_in[8];
    const float* bo    = (const float*)d_in[9];
    const float* ln1g  = (const float*)d_in[10];
    const float* ln1b  = (const float*)d_in[11];
    const float* Wi    = (const float*)d_in[12];
    const float* bi    = (const float*)d_in[13];
    const float* Wg    = (const float*)d_in[14];
    const float* bg    = (const float*)d_in[15];
    const float* Wl    = (const float*)d_in[16];
    const float* bl    = (const float*)d_in[17];
    const float* Wf    = (const float*)d_in[18];
    const float* bf    = (const float*)d_in[19];
    const float* ln2g  = (const float*)d_in[20];
    const float* ln2b  = (const float*)d_in[21];
    float* out = (float*)d_out;

    float *pk, *pv, *pq, *ps, *pcat, *pt1, *px, *pin, *pg1, *pg2;
    cudaGetSymbolAddress((void**)&pk,   g_k);
    cudaGetSymbolAddress((void**)&pv,   g_v);
    cudaGetSymbolAddress((void**)&pq,   g_q);
    cudaGetSymbolAddress((void**)&ps,   g_s);
    cudaGetSymbolAddress((void**)&pcat, g_cat);
    cudaGetSymbolAddress((void**)&pt1,  g_t1);
    cudaGetSymbolAddress((void**)&px,   g_x);
    cudaGetSymbolAddress((void**)&pin,  g_in);
    cudaGetSymbolAddress((void**)&pg1,  g_g1);
    cudaGetSymbolAddress((void**)&pg2,  g_g2);

    // opt-in to >48KB dynamic smem for each instantiation used
    cudaFuncSetAttribute(gemm_tf32<AMODE_CONCAT, BMODE_N, false>,
                         cudaFuncAttributeMaxDynamicSharedMemorySize, SMEM_N_BYTES);
    cudaFuncSetAttribute(gemm_tf32<AMODE_DIRECT, BMODE_N, false>,
                         cudaFuncAttributeMaxDynamicSharedMemorySize, SMEM_N_BYTES);
    cudaFuncSetAttribute(gemm_tf32<AMODE_DIRECT, BMODE_N, true>,
                         cudaFuncAttributeMaxDynamicSharedMemorySize, SMEM_N_BYTES);
    cudaFuncSetAttribute(gemm_tf32<AMODE_DIRECT, BMODE_T, false>,
                         cudaFuncAttributeMaxDynamicSharedMemorySize, SMEM_T_BYTES);

    const long long LL512x1024  = 512LL * 1024;
    const long long LL512x2048  = 512LL * 2048;
    const long long LL2048x1024 = 2048LL * 1024;

    // 1-2: k, v = concat(state,input) @ W + b   [8192,1024]
    gemm_tf32<AMODE_CONCAT, BMODE_N, false><<<dim3(8, 64, 1), 256, SMEM_N_BYTES>>>(
        state, input, Wk, bk, pk, 8192, 1024, 1024, 1024, 1024, 1024,
        1, 0, 0, 0, 0, 0, 0, 0, 1.0f);
    gemm_tf32<AMODE_CONCAT, BMODE_N, false><<<dim3(8, 64, 1), 256, SMEM_N_BYTES>>>(
        state, input, Wv, bv, pv, 8192, 1024, 1024, 1024, 1024, 1024,
        1, 0, 0, 0, 0, 0, 0, 0, 1.0f);

    // 3: q[b,h] = state[b] @ Wq[h] + bq[h]   (z = b*8+h)
    gemm_tf32<AMODE_DIRECT, BMODE_N, false><<<dim3(8, 4, 32), 256, SMEM_N_BYTES>>>(
        state, (const float*)0, Wq, bq, pq, 512, 1024, 1024, 1024, 1024, 1024,
        8, LL512x1024, 0, 0, 1024LL * 1024, 8 * LL512x1024, LL512x1024, 1024, 1.0f);

    // 4: scores[b,h] = q[b,h] @ k[b]^T / 32   (B K-contiguous -> ldmatrix path)
    gemm_tf32<AMODE_DIRECT, BMODE_T, false><<<dim3(16, 4, 32), 256, SMEM_T_BYTES>>>(
        pq, (const float*)0, pk, (const float*)0, ps, 512, 2048, 1024, 1024, 1024, 2048,
        8, 8 * LL512x1024, LL512x1024, LL2048x1024, 0, 8 * LL512x2048, LL512x2048, 0,
        0.03125f);

    // 5: softmax over T
    softmax2048<<<4 * 8 * 512, 256>>>(ps);

    // 6: ctx[b,h] = attn[b,h] @ v[b]  -> written directly in concat layout [B,S,H*D]
    gemm_tf32<AMODE_DIRECT, BMODE_N, false><<<dim3(8, 4, 32), 256, SMEM_N_BYTES>>>(
        ps, (const float*)0, pv, (const float*)0, pcat, 512, 1024, 2048, 2048, 1024, 8192,
        8, 8 * LL512x2048, LL512x2048, LL2048x1024, 0, 512LL * 8192, 1024, 0, 1.0f);

    // 7: attn_out = concat @ Wo + bo   [2048,1024]
    gemm_tf32<AMODE_DIRECT, BMODE_N, false><<<dim3(8, 16, 1), 256, SMEM_N_BYTES>>>(
        pcat, (const float*)0, Wo, bo, pt1, 2048, 1024, 8192, 8192, 1024, 1024,
        1, 0, 0, 0, 0, 0, 0, 0, 1.0f);

    // 8: x = LN(attn_out + state)
    add_ln1024<<<2048, 256>>>(pt1, state, ln1g, ln1b, px);

    // 9: inner = relu(x @ Wi + bi)   [2048,4096]
    gemm_tf32<AMODE_DIRECT, BMODE_N, true><<<dim3(32, 16, 1), 256, SMEM_N_BYTES>>>(
        px, (const float*)0, Wi, bi, pin, 2048, 4096, 1024, 1024, 4096, 4096,
        1, 0, 0, 0, 0, 0, 0, 0, 1.0f);

    // 10-11: g1 = inner @ Wg + bg ; g2 = inner @ Wl + bl
    gemm_tf32<AMODE_DIRECT, BMODE_N, false><<<dim3(32, 16, 1), 256, SMEM_N_BYTES>>>(
        pin, (const float*)0, Wg, bg, pg1, 2048, 4096, 4096, 4096, 4096, 4096,
        1, 0, 0, 0, 0, 0, 0, 0, 1.0f);
    gemm_tf32<AMODE_DIRECT, BMODE_N, false><<<dim3(32, 16, 1), 256, SMEM_N_BYTES>>>(
        pin, (const float*)0, Wl, bl, pg2, 2048, 4096, 4096, 4096, 4096, 4096,
        1, 0, 0, 0, 0, 0, 0, 0, 1.0f);

    // 12: gated = relu(g1) * g2 (into g1)
    gated_mul<<<8192, 256>>>(pg1, pg2);

    // 13: ff = gated @ Wf + bf   [2048,1024]
    gemm_tf32<AMODE_DIRECT, BMODE_N, false><<<dim3(8, 16, 1), 256, SMEM_N_BYTES>>>(
        pg1, (const float*)0, Wf, bf, pt1, 2048, 1024, 4096, 4096, 1024, 1024,
        1, 0, 0, 0, 0, 0, 0, 0, 1.0f);

    // 14: out = LN(ff + x)
    add_ln1024<<<2048, 256>>>(pt1, px, ln2g, ln2b, out);
}

// round 14
// speedup vs baseline: 1.2850x; 1.0207x over previous
#include <cuda_runtime.h>

// ---------------------------------------------------------------------------
// StateTransformerBlock on GB300 — round 13 kernel (resubmit): tf32 mma.sync +
// ldmatrix + 3-stage cp.async, 64x64 warp tiles (128 threads/CTA, 2x2 warps).
// B=4, S_STATE=512, S_IN=1536, T=2048, D=1024, H=8, F=4096. All fp32 I/O.
// ---------------------------------------------------------------------------

#define DEV_INLINE __device__ __forceinline__

namespace stb {

constexpr int Bn      = 4;
constexpr int S_ST    = 512;
constexpr int S_INP   = 1536;
constexpr int Tn      = 2048;   // S_ST + S_INP
constexpr int Dn      = 1024;
constexpr int Hn      = 8;
constexpr int Fn      = 4096;

// ---------------- scratch (device globals; no allocation allowed) ----------
__device__ __align__(128) float g_k  [Bn * Tn * Dn];
__device__ __align__(128) float g_v  [Bn * Tn * Dn];
__device__ __align__(128) float g_q  [Bn * Hn * S_ST * Dn];
__device__ __align__(128) float g_s  [(long long)Bn * Hn * S_ST * Tn];
__device__ __align__(128) float g_cat[Bn * S_ST * Hn * Dn];
__device__ __align__(128) float g_t1 [Bn * S_ST * Dn];
__device__ __align__(128) float g_x  [Bn * S_ST * Dn];
__device__ __align__(128) float g_in [Bn * S_ST * Fn];
__device__ __align__(128) float g_g1 [Bn * S_ST * Fn];
__device__ __align__(128) float g_g2 [Bn * S_ST * Fn];

// ---------------- GEMM config ----------------------------------------------
constexpr int BM = 128, BN = 128, BK = 16;
constexpr int STAGES = 3;
constexpr int LDMK  = BK + 4;      // 20 words: ldmatrix rows hit distinct 16B groups
constexpr int LDB_S = BN + 8;      // 136 words: scalar B-frag LDS conflict-free
constexpr int NTHREADS = 128;      // 4 warps, 2(m) x 2(n) grid, 64x64 per warp

enum { AMODE_DIRECT = 0, AMODE_CONCAT = 1 };
enum { BMODE_N = 0, BMODE_T = 1 };    // N: B[k][n] n-contig;  T: B[n][k] k-contig

DEV_INLINE unsigned f2tfu(unsigned x) {
    unsigned r;
    asm("cvt.rna.tf32.f32 %0, %1;" : "=r"(r) : "f"(__uint_as_float(x)));
    return r;
}

DEV_INLINE void ldsm_x4(unsigned& r0, unsigned& r1, unsigned& r2, unsigned& r3,
                        unsigned addr) {
    asm volatile("ldmatrix.sync.aligned.m8n8.x4.shared.b16 {%0,%1,%2,%3}, [%4];"
                 : "=r"(r0), "=r"(r1), "=r"(r2), "=r"(r3) : "r"(addr));
}

#define CP_ASYNC16(DST_, SRC_) \
    asm volatile("cp.async.cg.shared.global [%0], [%1], 16;" :: "r"(DST_), "l"(SRC_))
#define CP_COMMIT() asm volatile("cp.async.commit_group;")
#define CP_WAIT(N_) asm volatile("cp.async.wait_group %0;" :: "n"(N_))

// smem bytes per instantiation (host + device)
constexpr int A_BUF_B   = BM * LDMK * 4;           // 10240
constexpr int B_BUF_T_B = BN * LDMK * 4;           // 10240
constexpr int B_BUF_N_B = BK * LDB_S * 4;          // 8704
constexpr int SMEM_T_BYTES = STAGES * (A_BUF_B + B_BUF_T_B);   // 61440
constexpr int SMEM_N_BYTES = STAGES * (A_BUF_B + B_BUF_N_B);   // 56832

// A row-major [M,K] (or CONCAT-gathered rows of length 1024).
// BMODE_N: B row-major [K,N]. BMODE_T: element (k,n) at B[n*ldb + k].
// C row-major [M,N]. Batched over blockIdx.z: z -> (zb = z/ZH, zh = z%ZH).
template <int AM, int BMODE, bool RELU>
__global__ void __launch_bounds__(NTHREADS, 2)
gemm_tf32(const float* __restrict__ A, const float* __restrict__ A2,
          const float* __restrict__ Bmat, const float* __restrict__ bias,
          float* __restrict__ C,
          int M, int N, int K, int lda, int ldb, int ldc, int ZH,
          long long aSB, long long aSH, long long bSB, long long bSH,
          long long cSB, long long cSH, long long biasSH, float scale)
{
    extern __shared__ __align__(16) unsigned smem_u[];
    constexpr int BS_ROWS = (BMODE == BMODE_T) ? BN : BK;
    constexpr int BS_LD   = (BMODE == BMODE_T) ? LDMK : LDB_S;
    constexpr unsigned A_BUF = BM * LDMK * 4;       // bytes per A stage
    constexpr unsigned B_BUF = BS_ROWS * BS_LD * 4; // bytes per B stage

    unsigned* Asm = smem_u;                               // STAGES*BM*LDMK words
    unsigned* Bsm = smem_u + STAGES * BM * LDMK;          // STAGES*BS_ROWS*BS_LD

    const int z  = blockIdx.z;
    const int zb = z / ZH, zh = z - zb * ZH;
    const float* Ab = A    + zb * aSB + zh * aSH;
    const float* Bb = Bmat + zb * bSB + zh * bSH;
    float*       Cb = C    + zb * cSB + zh * cSH;
    const float* biasb = bias ? (bias + zh * biasSH) : (const float*)0;

    const int m0 = blockIdx.y * BM;
    const int n0 = blockIdx.x * BN;
    const int tid  = threadIdx.x;
    const int lane = tid & 31;
    const int warp = tid >> 5;        // 0..3
    const int wm = warp & 1;          // 2 warps along M (64 rows each)
    const int wn = warp >> 1;         // 2 warps along N (64 cols each)
    const int g   = lane >> 2;        // groupID 0..7
    const int tig = lane & 3;         // threadInGroup 0..3

    // staging maps (128 threads)
    const int srow = tid;             // A (and B-T) staged row 0..127, full row/thread
    const int bcv  = tid & 31;        // B(N) float4 column
    const int brow = tid >> 5;        // B(N) base k-row 0..3 (4 rows per thread)

    // A row base pointer (constant across the k loop)
    const float* aRow;
    if (AM == AMODE_CONCAT) {
        const int m = m0 + srow;
        const int b = m >> 11;        // / 2048
        const int t = m & 2047;
        aRow = (t < S_ST) ? (A  + ((long long)b * S_ST  + t)          * Dn)
                          : (A2 + ((long long)b * S_INP + (t - S_ST)) * Dn);
    } else {
        aRow = Ab + (long long)(m0 + srow) * lda;
    }
    const float* bTrow = Bb + (long long)(n0 + srow) * ldb;  // BMODE_T only

    // shared-space base addresses
    const unsigned aSm = (unsigned)__cvta_generic_to_shared(Asm);
    const unsigned bSm = (unsigned)__cvta_generic_to_shared(Bsm);

    // per-thread staging destination offsets (within one stage)
    const unsigned aStOff = (unsigned)(srow * LDMK) * 4;   // word 0 of this row

    // ldmatrix per-thread fragment offsets (within one stage)
    // A: row = wm*64 + i*16 + (lane&15), col = ks*8 + (lane>>4)*4
    const unsigned aOff = ((wm * 64 + (lane & 15)) * LDMK + (lane >> 4) * 4) * 4;
    // B(T): row n = wn*64 + jp*16 + (lane&7) + (lane>>4)*8, col = ks*8 + ((lane>>3)&1)*4
    const unsigned bOff = ((wn * 64 + (lane & 7) + (lane >> 4) * 8) * LDMK
                           + ((lane >> 3) & 1) * 4) * 4;

    const int NT = K / BK;

#define GEMM_COPY(K0_, S_)                                                      \
    do {                                                                        \
        const unsigned a0 = aSm + (unsigned)(S_) * A_BUF + aStOff;              \
        _Pragma("unroll")                                                       \
        for (int c = 0; c < 4; ++c)                                             \
            CP_ASYNC16(a0 + (unsigned)c * 16, aRow + (K0_) + c * 4);            \
        if (BMODE == BMODE_N) {                                                 \
            _Pragma("unroll")                                                   \
            for (int it = 0; it < 4; ++it) {                                    \
                const int kr = brow + it * 4;                                   \
                CP_ASYNC16(bSm + (unsigned)(S_) * B_BUF                         \
                               + (unsigned)(kr * BS_LD + bcv * 4) * 4,          \
                           Bb + (long long)((K0_) + kr) * ldb + n0 + bcv * 4);  \
            }                                                                   \
        } else {                                                                \
            const unsigned b0 = bSm + (unsigned)(S_) * B_BUF + aStOff;          \
            _Pragma("unroll")                                                   \
            for (int c = 0; c < 4; ++c)                                         \
                CP_ASYNC16(b0 + (unsigned)c * 16, bTrow + (K0_) + c * 4);       \
        }                                                                       \
    } while (0)

    float acc[4][8][4];
#pragma unroll
    for (int i = 0; i < 4; ++i)
#pragma unroll
        for (int j = 0; j < 8; ++j)
#pragma unroll
            for (int c = 0; c < 4; ++c) acc[i][j][c] = 0.0f;

    // prefetch STAGES-1 stages
#pragma unroll
    for (int s = 0; s < STAGES - 1; ++s) {
        GEMM_COPY(s * BK, s);
        CP_COMMIT();
    }

    for (int kt = 0; kt < NT; ++kt) {
        CP_WAIT(STAGES - 2);          // stage kt's copy complete
        __syncthreads();              // all warps done with stage (kt+2)%3 reads

        const int nk = kt + STAGES - 1;
        if (nk < NT) GEMM_COPY(nk * BK, nk % STAGES);
        CP_COMMIT();                  // commit (possibly empty) to keep counts aligned

        const int buf = kt % STAGES;
        const unsigned aStage = aSm + (unsigned)buf * A_BUF;
        const unsigned bStage = bSm + (unsigned)buf * B_BUF;

#pragma unroll
        for (int ks = 0; ks < 2; ++ks) {
            const int kb = ks * 8;
            unsigned af[4][4], bf[8][2];
            // A fragments via ldmatrix.x4 (one per 16-row m tile), then cvt
#pragma unroll
            for (int i = 0; i < 4; ++i) {
                const unsigned addr = aStage + aOff
                                    + (unsigned)i * (16 * LDMK * 4)
                                    + (unsigned)ks * 32;
                ldsm_x4(af[i][0], af[i][1], af[i][2], af[i][3], addr);
#pragma unroll
                for (int r = 0; r < 4; ++r) af[i][r] = f2tfu(af[i][r]);
            }
            if (BMODE == BMODE_T) {
#pragma unroll
                for (int jp = 0; jp < 4; ++jp) {
                    const unsigned addr = bStage + bOff
                                        + (unsigned)jp * (16 * LDMK * 4)
                                        + (unsigned)ks * 32;
                    ldsm_x4(bf[2 * jp][0], bf[2 * jp][1],
                            bf[2 * jp + 1][0], bf[2 * jp + 1][1], addr);
                }
#pragma unroll
                for (int j = 0; j < 8; ++j) {
                    bf[j][0] = f2tfu(bf[j][0]);
                    bf[j][1] = f2tfu(bf[j][1]);
                }
            } else {
#pragma unroll
                for (int j = 0; j < 8; ++j) {
                    const int nc = wn * 64 + j * 8;
                    bf[j][0] = f2tfu(Bsm[(buf * BS_ROWS + kb + tig    ) * BS_LD + nc + g]);
                    bf[j][1] = f2tfu(Bsm[(buf * BS_ROWS + kb + tig + 4) * BS_LD + nc + g]);
                }
            }
#pragma unroll
            for (int i = 0; i < 4; ++i)
#pragma unroll
                for (int j = 0; j < 8; ++j)
                    asm volatile(
                        "mma.sync.aligned.m16n8k8.row.col.f32.tf32.tf32.f32 "
                        "{%0,%1,%2,%3}, {%4,%5,%6,%7}, {%8,%9}, {%0,%1,%2,%3};\n"
                        : "+f"(acc[i][j][0]), "+f"(acc[i][j][1]),
                          "+f"(acc[i][j][2]), "+f"(acc[i][j][3])
                        : "r"(af[i][0]), "r"(af[i][1]), "r"(af[i][2]), "r"(af[i][3]),
                          "r"(bf[j][0]), "r"(bf[j][1]));
        }
    }
#undef GEMM_COPY

    // epilogue
#pragma unroll
    for (int i = 0; i < 4; ++i) {
        const int r0 = m0 + wm * 64 + i * 16 + g;
#pragma unroll
        for (int j = 0; j < 8; ++j) {
            const int c0 = n0 + wn * 64 + j * 8 + tig * 2;
            float v0 = acc[i][j][0] * scale;
            float v1 = acc[i][j][1] * scale;
            float v2 = acc[i][j][2] * scale;
            float v3 = acc[i][j][3] * scale;
            if (biasb) {
                const float b0 = biasb[c0], b1 = biasb[c0 + 1];
                v0 += b0; v1 += b1; v2 += b0; v3 += b1;
            }
            if (RELU) {
                v0 = fmaxf(v0, 0.0f); v1 = fmaxf(v1, 0.0f);
                v2 = fmaxf(v2, 0.0f); v3 = fmaxf(v3, 0.0f);
            }
            *(float2*)(Cb + (long long)r0       * ldc + c0) = make_float2(v0, v1);
            *(float2*)(Cb + (long long)(r0 + 8) * ldc + c0) = make_float2(v2, v3);
        }
    }
}

// ---------------- softmax over rows of length 2048 --------------------------
__global__ void softmax2048(float* __restrict__ data)
{
    float* p = data + (long long)blockIdx.x * 2048;
    const int tid = threadIdx.x;
    const int lane = tid & 31, warp = tid >> 5;

    __shared__ float redA[8];
    __shared__ float redB[8];

    float v[8];
    float mx = -3.0e38f;
#pragma unroll
    for (int i = 0; i < 8; ++i) { v[i] = p[tid + i * 256]; mx = fmaxf(mx, v[i]); }
#pragma unroll
    for (int o = 16; o; o >>= 1) mx = fmaxf(mx, __shfl_xor_sync(0xffffffffu, mx, o));
    if (lane == 0) redA[warp] = mx;
    __syncthreads();
    if (tid < 32) {
        float m2 = (tid < 8) ? redA[tid] : -3.0e38f;
#pragma unroll
        for (int o = 4; o; o >>= 1) m2 = fmaxf(m2, __shfl_xor_sync(0xffffffffu, m2, o));
        if (tid == 0) redB[0] = m2;
    }
    __syncthreads();
    mx = redB[0];

    float s = 0.0f;
#pragma unroll
    for (int i = 0; i < 8; ++i) { v[i] = __expf(v[i] - mx); s += v[i]; }
#pragma unroll
    for (int o = 16; o; o >>= 1) s += __shfl_xor_sync(0xffffffffu, s, o);
    if (lane == 0) redA[warp] = s;
    __syncthreads();
    if (tid < 32) {
        float s2 = (tid < 8) ? redA[tid] : 0.0f;
#pragma unroll
        for (int o = 4; o; o >>= 1) s2 += __shfl_xor_sync(0xffffffffu, s2, o);
        if (tid == 0) redB[1] = s2;
    }
    __syncthreads();
    const float inv = 1.0f / redB[1];
#pragma unroll
    for (int i = 0; i < 8; ++i) p[tid + i * 256] = v[i] * inv;
}

// ---------------- out = LayerNorm(a + r) over D=1024 ------------------------
__global__ void add_ln1024(const float* __restrict__ a, const float* __restrict__ r,
                           const float* __restrict__ gw, const float* __restrict__ bw,
                           float* __restrict__ out)
{
    const long long base = (long long)blockIdx.x * 1024;
    const int tid = threadIdx.x;
    const int lane = tid & 31, warp = tid >> 5;

    __shared__ float rs[8], rq[8];
    __shared__ float fin[2];

    float v[4];
    float s = 0.0f, sq = 0.0f;
#pragma unroll
    for (int i = 0; i < 4; ++i) {
        const int c = tid + i * 256;
        const float x = a[base + c] + r[base + c];
        v[i] = x; s += x; sq += x * x;
    }
#pragma unroll
    for (int o = 16; o; o >>= 1) {
        s  += __shfl_xor_sync(0xffffffffu, s,  o);
        sq += __shfl_xor_sync(0xffffffffu, sq, o);
    }
    if (lane == 0) { rs[warp] = s; rq[warp] = sq; }
    __syncthreads();
    if (tid < 32) {
        float s2 = (tid < 8) ? rs[tid] : 0.0f;
        float q2 = (tid < 8) ? rq[tid] : 0.0f;
#pragma unroll
        for (int o = 4; o; o >>= 1) {
            s2 += __shfl_xor_sync(0xffffffffu, s2, o);
            q2 += __shfl_xor_sync(0xffffffffu, q2, o);
        }
        if (tid == 0) { fin[0] = s2; fin[1] = q2; }
    }
    __syncthreads();
    const float mean = fin[0] * (1.0f / 1024.0f);
    float var = fin[1] * (1.0f / 1024.0f) - mean * mean;
    var = fmaxf(var, 0.0f);
    const float inv = rsqrtf(var + 1e-6f);
#pragma unroll
    for (int i = 0; i < 4; ++i) {
        const int c = tid + i * 256;
        out[base + c] = (v[i] - mean) * inv * gw[c] + bw[c];
    }
}

// ---------------- gated = relu(g1) * g2 (in place into g1) ------------------
__global__ void gated_mul(float* __restrict__ a, const float* __restrict__ b)
{
    const long long i = ((long long)blockIdx.x * 256 + threadIdx.x) * 4;
    float4 x = *(const float4*)(a + i);
    const float4 y = *(const float4*)(b + i);
    x.x = fmaxf(x.x, 0.0f) * y.x;
    x.y = fmaxf(x.y, 0.0f) * y.y;
    x.z = fmaxf(x.z, 0.0f) * y.z;
    x.w = fmaxf(x.w, 0.0f) * y.w;
    *(float4*)(a + i) = x;
}

} // namespace stb

// ---------------------------------------------------------------------------
extern "C" void kernel_launch(void* const* d_in, const int* in_sizes, int n_in,
                              void* d_out, int out_size)
{
    using namespace stb;
    (void)in_sizes; (void)n_in; (void)out_size;

    const float* state = (const float*)d_in[0];
    const float* input = (const float*)d_in[1];
    const float* Wk    = (const float*)d_in[2];
    const float* bk    = (const float*)d_in[3];
    const float* Wv    = (const float*)d_in[4];
    const float* bv    = (const float*)d_in[5];
    const float* Wq    = (const float*)d_in[6];
    const float* bq    = (const float*)d_in[7];
    const float* Wo    = (const float*)d_in[8];
    const float* bo    = (const float*)d_in[9];
    const float* ln1g  = (const float*)d_in[10];
    const float* ln1b  = (const float*)d_in[11];
    const float* Wi    = (const float*)d_in[12];
    const float* bi    = (const float*)d_in[13];
    const float* Wg    = (const float*)d_in[14];
    const float* bg    = (const float*)d_in[15];
    const float* Wl    = (const float*)d_in[16];
    const float* bl    = (const float*)d_in[17];
    const float* Wf    = (const float*)d_in[18];
    const float* bf    = (const float*)d_in[19];
    const float* ln2g  = (const float*)d_in[20];
    const float* ln2b  = (const float*)d_in[21];
    float* out = (float*)d_out;

    float *pk, *pv, *pq, *ps, *pcat, *pt1, *px, *pin, *pg1, *pg2;
    cudaGetSymbolAddress((void**)&pk,   g_k);
    cudaGetSymbolAddress((void**)&pv,   g_v);
    cudaGetSymbolAddress((void**)&pq,   g_q);
    cudaGetSymbolAddress((void**)&ps,   g_s);
    cudaGetSymbolAddress((void**)&pcat, g_cat);
    cudaGetSymbolAddress((void**)&pt1,  g_t1);
    cudaGetSymbolAddress((void**)&px,   g_x);
    cudaGetSymbolAddress((void**)&pin,  g_in);
    cudaGetSymbolAddress((void**)&pg1,  g_g1);
    cudaGetSymbolAddress((void**)&pg2,  g_g2);

    // opt-in to >48KB dynamic smem for each instantiation used
    cudaFuncSetAttribute(gemm_tf32<AMODE_CONCAT, BMODE_N, false>,
                         cudaFuncAttributeMaxDynamicSharedMemorySize, SMEM_N_BYTES);
    cudaFuncSetAttribute(gemm_tf32<AMODE_DIRECT, BMODE_N, false>,
                         cudaFuncAttributeMaxDynamicSharedMemorySize, SMEM_N_BYTES);
    cudaFuncSetAttribute(gemm_tf32<AMODE_DIRECT, BMODE_N, true>,
                         cudaFuncAttributeMaxDynamicSharedMemorySize, SMEM_N_BYTES);
    cudaFuncSetAttribute(gemm_tf32<AMODE_DIRECT, BMODE_T, false>,
                         cudaFuncAttributeMaxDynamicSharedMemorySize, SMEM_T_BYTES);

    const long long LL512x1024  = 512LL * 1024;
    const long long LL512x2048  = 512LL * 2048;
    const long long LL2048x1024 = 2048LL * 1024;

    // 1-2: k, v = concat(state,input) @ W + b   [8192,1024]
    gemm_tf32<AMODE_CONCAT, BMODE_N, false><<<dim3(8, 64, 1), NTHREADS, SMEM_N_BYTES>>>(
        state, input, Wk, bk, pk, 8192, 1024, 1024, 1024, 1024, 1024,
        1, 0, 0, 0, 0, 0, 0, 0, 1.0f);
    gemm_tf32<AMODE_CONCAT, BMODE_N, false><<<dim3(8, 64, 1), NTHREADS, SMEM_N_BYTES>>>(
        state, input, Wv, bv, pv, 8192, 1024, 1024, 1024, 1024, 1024,
        1, 0, 0, 0, 0, 0, 0, 0, 1.0f);

    // 3: q[b,h] = state[b] @ Wq[h] + bq[h]   (z = b*8+h)
    gemm_tf32<AMODE_DIRECT, BMODE_N, false><<<dim3(8, 4, 32), NTHREADS, SMEM_N_BYTES>>>(
        state, (const float*)0, Wq, bq, pq, 512, 1024, 1024, 1024, 1024, 1024,
        8, LL512x1024, 0, 0, 1024LL * 1024, 8 * LL512x1024, LL512x1024, 1024, 1.0f);

    // 4: scores[b,h] = q[b,h] @ k[b]^T / 32   (B K-contiguous -> ldmatrix path)
    gemm_tf32<AMODE_DIRECT, BMODE_T, false><<<dim3(16, 4, 32), NTHREADS, SMEM_T_BYTES>>>(
        pq, (const float*)0, pk, (const float*)0, ps, 512, 2048, 1024, 1024, 1024, 2048,
        8, 8 * LL512x1024, LL512x1024, LL2048x1024, 0, 8 * LL512x2048, LL512x2048, 0,
        0.03125f);

    // 5: softmax over T
    softmax2048<<<4 * 8 * 512, 256>>>(ps);

    // 6: ctx[b,h] = attn[b,h] @ v[b]  -> written directly in concat layout [B,S,H*D]
    gemm_tf32<AMODE_DIRECT, BMODE_N, false><<<dim3(8, 4, 32), NTHREADS, SMEM_N_BYTES>>>(
        ps, (const float*)0, pv, (const float*)0, pcat, 512, 1024, 2048, 2048, 1024, 8192,
        8, 8 * LL512x2048, LL512x2048, LL2048x1024, 0, 512LL * 8192, 1024, 0, 1.0f);

    // 7: attn_out = concat @ Wo + bo   [2048,1024]
    gemm_tf32<AMODE_DIRECT, BMODE_N, false><<<dim3(8, 16, 1), NTHREADS, SMEM_N_BYTES>>>(
        pcat, (const float*)0, Wo, bo, pt1, 2048, 1024, 8192, 8192, 1024, 1024,
        1, 0, 0, 0, 0, 0, 0, 0, 1.0f);

    // 8: x = LN(attn_out + state)
    add_ln1024<<<2048, 256>>>(pt1, state, ln1g, ln1b, px);

    // 9: inner = relu(x @ Wi + bi)   [2048,4096]
    gemm_tf32<AMODE_DIRECT, BMODE_N, true><<<dim3(32, 16, 1), NTHREADS, SMEM_N_BYTES>>>(
        px, (const float*)0, Wi, bi, pin, 2048, 4096, 1024, 1024, 4096, 4096,
        1, 0, 0, 0, 0, 0, 0, 0, 1.0f);

    // 10-11: g1 = inner @ Wg + bg ; g2 = inner @ Wl + bl
    gemm_tf32<AMODE_DIRECT, BMODE_N, false><<<dim3(32, 16, 1), NTHREADS, SMEM_N_BYTES>>>(
        pin, (const float*)0, Wg, bg, pg1, 2048, 4096, 4096, 4096, 4096, 4096,
        1, 0, 0, 0, 0, 0, 0, 0, 1.0f);
    gemm_tf32<AMODE_DIRECT, BMODE_N, false><<<dim3(32, 16, 1), NTHREADS, SMEM_N_BYTES>>>(
        pin, (const float*)0, Wl, bl, pg2, 2048, 4096, 4096, 4096, 4096, 4096,
        1, 0, 0, 0, 0, 0, 0, 0, 1.0f);

    // 12: gated = relu(g1) * g2 (into g1)
    gated_mul<<<8192, 256>>>(pg1, pg2);

    // 13: ff = gated @ Wf + bf   [2048,1024]
    gemm_tf32<AMODE_DIRECT, BMODE_N, false><<<dim3(8, 16, 1), NTHREADS, SMEM_N_BYTES>>>(
        pg1, (const float*)0, Wf, bf, pt1, 2048, 1024, 4096, 4096, 1024, 1024,
        1, 0, 0, 0, 0, 0, 0, 0, 1.0f);

    // 14: out = LN(ff + x)
    add_ln1024<<<2048, 256>>>(pt1, px, ln2g, ln2b, out);
}

// round 15
// speedup vs baseline: 1.4329x; 1.1151x over previous
#include <cuda_runtime.h>

// ---------------------------------------------------------------------------
// StateTransformerBlock on GB300 — round 15: tf32 mma.sync + ldmatrix +
// 3-stage cp.async, 64x64 warp tiles, PRE-CONVERTED tf32 operands
// (zero cvt in GEMM hot loop). B=4, T=2048, D=1024, H=8, F=4096. fp32 I/O.
// ---------------------------------------------------------------------------

#define DEV_INLINE __device__ __forceinline__

namespace stb {

constexpr int Bn      = 4;
constexpr int S_ST    = 512;
constexpr int S_INP   = 1536;
constexpr int Tn      = 2048;
constexpr int Dn      = 1024;
constexpr int Hn      = 8;
constexpr int Fn      = 4096;

// ---------------- scratch (device globals; no allocation allowed) ----------
__device__ __align__(128) float g_k  [Bn * Tn * Dn];
__device__ __align__(128) float g_v  [Bn * Tn * Dn];
__device__ __align__(128) float g_q  [Bn * Hn * S_ST * Dn];
__device__ __align__(128) float g_s  [(long long)Bn * Hn * S_ST * Tn];
__device__ __align__(128) float g_cat[Bn * S_ST * Hn * Dn];
__device__ __align__(128) float g_t1 [Bn * S_ST * Dn];
__device__ __align__(128) float g_x  [Bn * S_ST * Dn];
__device__ __align__(128) float g_xt [Bn * S_ST * Dn];      // tf32 copy of x
__device__ __align__(128) float g_in [Bn * S_ST * Fn];
__device__ __align__(128) float g_g1 [Bn * S_ST * Fn];
__device__ __align__(128) float g_g2 [Bn * S_ST * Fn];
// pre-converted tf32 operands
__device__ __align__(128) float g_cst[Bn * S_ST * Dn];
__device__ __align__(128) float g_cin[Bn * S_INP * Dn];
__device__ __align__(128) float g_cWk[Dn * Dn];
__device__ __align__(128) float g_cWv[Dn * Dn];
__device__ __align__(128) float g_cWq[Hn * Dn * Dn];
__device__ __align__(128) float g_cWo[Hn * Dn * Dn];
__device__ __align__(128) float g_cWi[Dn * Fn];
__device__ __align__(128) float g_cWg[Fn * Fn];
__device__ __align__(128) float g_cWl[Fn * Fn];
__device__ __align__(128) float g_cWf[Fn * Dn];

// ---------------- GEMM config ----------------------------------------------
constexpr int BM = 128, BN = 128, BK = 16;
constexpr int STAGES = 3;
constexpr int LDMK  = BK + 4;      // 20 words: ldmatrix rows hit distinct 16B groups
constexpr int LDB_S = BN + 8;      // 136 words: scalar B-frag LDS conflict-free
constexpr int NTHREADS = 128;      // 4 warps, 2(m) x 2(n), 64x64 per warp

enum { AMODE_DIRECT = 0, AMODE_CONCAT = 1 };
enum { BMODE_N = 0, BMODE_T = 1 };

DEV_INLINE unsigned f2tfu(unsigned x) {
    unsigned r;
    asm("cvt.rna.tf32.f32 %0, %1;" : "=r"(r) : "f"(__uint_as_float(x)));
    return r;
}
DEV_INLINE float f2tff(float x) {
    return __uint_as_float(f2tfu(__float_as_uint(x)));
}

DEV_INLINE void ldsm_x4(unsigned& r0, unsigned& r1, unsigned& r2, unsigned& r3,
                        unsigned addr) {
    asm volatile("ldmatrix.sync.aligned.m8n8.x4.shared.b16 {%0,%1,%2,%3}, [%4];"
                 : "=r"(r0), "=r"(r1), "=r"(r2), "=r"(r3) : "r"(addr));
}

#define CP_ASYNC16(DST_, SRC_) \
    asm volatile("cp.async.cg.shared.global [%0], [%1], 16;" :: "r"(DST_), "l"(SRC_))
#define CP_COMMIT() asm volatile("cp.async.commit_group;")
#define CP_WAIT(N_) asm volatile("cp.async.wait_group %0;" :: "n"(N_))

constexpr int A_BUF_B   = BM * LDMK * 4;
constexpr int B_BUF_T_B = BN * LDMK * 4;
constexpr int B_BUF_N_B = BK * LDB_S * 4;
constexpr int SMEM_T_BYTES = STAGES * (A_BUF_B + B_BUF_T_B);   // 61440
constexpr int SMEM_N_BYTES = STAGES * (A_BUF_B + B_BUF_N_B);   // 56832

// All operands ALREADY tf32-rounded (stored as float bits). No cvt in loop.
template <int AM, int BMODE, bool RELU, bool CVTOUT>
__global__ void __launch_bounds__(NTHREADS, 2)
gemm_tf32(const float* __restrict__ A, const float* __restrict__ A2,
          const float* __restrict__ Bmat, const float* __restrict__ bias,
          float* __restrict__ C,
          int M, int N, int K, int lda, int ldb, int ldc, int ZH,
          long long aSB, long long aSH, long long bSB, long long bSH,
          long long cSB, long long cSH, long long biasSH, float scale)
{
    extern __shared__ __align__(16) unsigned smem_u[];
    constexpr int BS_ROWS = (BMODE == BMODE_T) ? BN : BK;
    constexpr int BS_LD   = (BMODE == BMODE_T) ? LDMK : LDB_S;
    constexpr unsigned A_BUF = BM * LDMK * 4;
    constexpr unsigned B_BUF = BS_ROWS * BS_LD * 4;

    unsigned* Asm = smem_u;
    unsigned* Bsm = smem_u + STAGES * BM * LDMK;

    const int z  = blockIdx.z;
    const int zb = z / ZH, zh = z - zb * ZH;
    const float* Ab = A    + zb * aSB + zh * aSH;
    const float* Bb = Bmat + zb * bSB + zh * bSH;
    float*       Cb = C    + zb * cSB + zh * cSH;
    const float* biasb = bias ? (bias + zh * biasSH) : (const float*)0;

    const int m0 = blockIdx.y * BM;
    const int n0 = blockIdx.x * BN;
    const int tid  = threadIdx.x;
    const int lane = tid & 31;
    const int warp = tid >> 5;
    const int wm = warp & 1;
    const int wn = warp >> 1;
    const int g   = lane >> 2;
    const int tig = lane & 3;

    const int srow = tid;
    const int bcv  = tid & 31;
    const int brow = tid >> 5;

    const float* aRow;
    if (AM == AMODE_CONCAT) {
        const int m = m0 + srow;
        const int b = m >> 11;
        const int t = m & 2047;
        aRow = (t < S_ST) ? (A  + ((long long)b * S_ST  + t)          * Dn)
                          : (A2 + ((long long)b * S_INP + (t - S_ST)) * Dn);
    } else {
        aRow = Ab + (long long)(m0 + srow) * lda;
    }
    const float* bTrow = Bb + (long long)(n0 + srow) * ldb;

    const unsigned aSm = (unsigned)__cvta_generic_to_shared(Asm);
    const unsigned bSm = (unsigned)__cvta_generic_to_shared(Bsm);

    const unsigned aStOff = (unsigned)(srow * LDMK) * 4;

    const unsigned aOff = ((wm * 64 + (lane & 15)) * LDMK + (lane >> 4) * 4) * 4;
    const unsigned bOff = ((wn * 64 + (lane & 7) + (lane >> 4) * 8) * LDMK
                           + ((lane >> 3) & 1) * 4) * 4;

    const int NT = K / BK;

#define GEMM_COPY(K0_, S_)                                                      \
    do {                                                                        \
        const unsigned a0 = aSm + (unsigned)(S_) * A_BUF + aStOff;              \
        _Pragma("unroll")                                                       \
        for (int c = 0; c < 4; ++c)                                             \
            CP_ASYNC16(a0 + (unsigned)c * 16, aRow + (K0_) + c * 4);            \
        if (BMODE == BMODE_N) {                                                 \
            _Pragma("unroll")                                                   \
            for (int it = 0; it < 4; ++it) {                                    \
                const int kr = brow + it * 4;                                   \
                CP_ASYNC16(bSm + (unsigned)(S_) * B_BUF                         \
                               + (unsigned)(kr * BS_LD + bcv * 4) * 4,          \
                           Bb + (long long)((K0_) + kr) * ldb + n0 + bcv * 4);  \
            }                                                                   \
        } else {                                                                \
            const unsigned b0 = bSm + (unsigned)(S_) * B_BUF + aStOff;          \
            _Pragma("unroll")                                                   \
            for (int c = 0; c < 4; ++c)                                         \
                CP_ASYNC16(b0 + (unsigned)c * 16, bTrow + (K0_) + c * 4);       \
        }                                                                       \
    } while (0)

    float acc[4][8][4];
#pragma unroll
    for (int i = 0; i < 4; ++i)
#pragma unroll
        for (int j = 0; j < 8; ++j)
#pragma unroll
            for (int c = 0; c < 4; ++c) acc[i][j][c] = 0.0f;

#pragma unroll
    for (int s = 0; s < STAGES - 1; ++s) {
        GEMM_COPY(s * BK, s);
        CP_COMMIT();
    }

    for (int kt = 0; kt < NT; ++kt) {
        CP_WAIT(STAGES - 2);
        __syncthreads();

        const int nk = kt + STAGES - 1;
        if (nk < NT) GEMM_COPY(nk * BK, nk % STAGES);
        CP_COMMIT();

        const int buf = kt % STAGES;
        const unsigned aStage = aSm + (unsigned)buf * A_BUF;
        const unsigned bStage = bSm + (unsigned)buf * B_BUF;

#pragma unroll
        for (int ks = 0; ks < 2; ++ks) {
            const int kb = ks * 8;
            unsigned af[4][4], bf[8][2];
#pragma unroll
            for (int i = 0; i < 4; ++i) {
                const unsigned addr = aStage + aOff
                                    + (unsigned)i * (16 * LDMK * 4)
                                    + (unsigned)ks * 32;
                ldsm_x4(af[i][0], af[i][1], af[i][2], af[i][3], addr);
            }
            if (BMODE == BMODE_T) {
#pragma unroll
                for (int jp = 0; jp < 4; ++jp) {
                    const unsigned addr = bStage + bOff
                                        + (unsigned)jp * (16 * LDMK * 4)
                                        + (unsigned)ks * 32;
                    ldsm_x4(bf[2 * jp][0], bf[2 * jp][1],
                            bf[2 * jp + 1][0], bf[2 * jp + 1][1], addr);
                }
            } else {
#pragma unroll
                for (int j = 0; j < 8; ++j) {
                    const int nc = wn * 64 + j * 8;
                    bf[j][0] = Bsm[(buf * BS_ROWS + kb + tig    ) * BS_LD + nc + g];
                    bf[j][1] = Bsm[(buf * BS_ROWS + kb + tig + 4) * BS_LD + nc + g];
                }
            }
#pragma unroll
            for (int i = 0; i < 4; ++i)
#pragma unroll
                for (int j = 0; j < 8; ++j)
                    asm volatile(
                        "mma.sync.aligned.m16n8k8.row.col.f32.tf32.tf32.f32 "
                        "{%0,%1,%2,%3}, {%4,%5,%6,%7}, {%8,%9}, {%0,%1,%2,%3};\n"
                        : "+f"(acc[i][j][0]), "+f"(acc[i][j][1]),
                          "+f"(acc[i][j][2]), "+f"(acc[i][j][3])
                        : "r"(af[i][0]), "r"(af[i][1]), "r"(af[i][2]), "r"(af[i][3]),
                          "r"(bf[j][0]), "r"(bf[j][1]));
        }
    }
#undef GEMM_COPY

    // epilogue
#pragma unroll
    for (int i = 0; i < 4; ++i) {
        const int r0 = m0 + wm * 64 + i * 16 + g;
#pragma unroll
        for (int j = 0; j < 8; ++j) {
            const int c0 = n0 + wn * 64 + j * 8 + tig * 2;
            float v0 = acc[i][j][0] * scale;
            float v1 = acc[i][j][1] * scale;
            float v2 = acc[i][j][2] * scale;
            float v3 = acc[i][j][3] * scale;
            if (biasb) {
                const float b0 = biasb[c0], b1 = biasb[c0 + 1];
                v0 += b0; v1 += b1; v2 += b0; v3 += b1;
            }
            if (RELU) {
                v0 = fmaxf(v0, 0.0f); v1 = fmaxf(v1, 0.0f);
                v2 = fmaxf(v2, 0.0f); v3 = fmaxf(v3, 0.0f);
            }
            if (CVTOUT) {
                v0 = f2tff(v0); v1 = f2tff(v1); v2 = f2tff(v2); v3 = f2tff(v3);
            }
            *(float2*)(Cb + (long long)r0       * ldc + c0) = make_float2(v0, v1);
            *(float2*)(Cb + (long long)(r0 + 8) * ldc + c0) = make_float2(v2, v3);
        }
    }
}

// ---------------- tf32 pre-convert (elementwise) ----------------------------
__global__ void cvt_tf32(const float* __restrict__ in, float* __restrict__ outp)
{
    const long long i = ((long long)blockIdx.x * 256 + threadIdx.x) * 4;
    float4 x = *(const float4*)(in + i);
    x.x = f2tff(x.x); x.y = f2tff(x.y); x.z = f2tff(x.z); x.w = f2tff(x.w);
    *(float4*)(outp + i) = x;
}

// ---------------- softmax over rows of length 2048; writes tf32 probs -------
__global__ void softmax2048(float* __restrict__ data)
{
    float* p = data + (long long)blockIdx.x * 2048;
    const int tid = threadIdx.x;
    const int lane = tid & 31, warp = tid >> 5;

    __shared__ float redA[8];
    __shared__ float redB[8];

    float v[8];
    float mx = -3.0e38f;
#pragma unroll
    for (int i = 0; i < 8; ++i) { v[i] = p[tid + i * 256]; mx = fmaxf(mx, v[i]); }
#pragma unroll
    for (int o = 16; o; o >>= 1) mx = fmaxf(mx, __shfl_xor_sync(0xffffffffu, mx, o));
    if (lane == 0) redA[warp] = mx;
    __syncthreads();
    if (tid < 32) {
        float m2 = (tid < 8) ? redA[tid] : -3.0e38f;
#pragma unroll
        for (int o = 4; o; o >>= 1) m2 = fmaxf(m2, __shfl_xor_sync(0xffffffffu, m2, o));
        if (tid == 0) redB[0] = m2;
    }
    __syncthreads();
    mx = redB[0];

    float s = 0.0f;
#pragma unroll
    for (int i = 0; i < 8; ++i) { v[i] = __expf(v[i] - mx); s += v[i]; }
#pragma unroll
    for (int o = 16; o; o >>= 1) s += __shfl_xor_sync(0xffffffffu, s, o);
    if (lane == 0) redA[warp] = s;
    __syncthreads();
    if (tid < 32) {
        float s2 = (tid < 8) ? redA[tid] : 0.0f;
#pragma unroll
        for (int o = 4; o; o >>= 1) s2 += __shfl_xor_sync(0xffffffffu, s2, o);
        if (tid == 0) redB[1] = s2;
    }
    __syncthreads();
    const float inv = 1.0f / redB[1];
#pragma unroll
    for (int i = 0; i < 8; ++i) p[tid + i * 256] = f2tff(v[i] * inv);
}

// ---------------- out = LayerNorm(a + r); optional tf32 twin -----------------
__global__ void add_ln1024(const float* __restrict__ a, const float* __restrict__ r,
                           const float* __restrict__ gw, const float* __restrict__ bw,
                           float* __restrict__ out, float* __restrict__ out_tf)
{
    const long long base = (long long)blockIdx.x * 1024;
    const int tid = threadIdx.x;
    const int lane = tid & 31, warp = tid >> 5;

    __shared__ float rs[8], rq[8];
    __shared__ float fin[2];

    float v[4];
    float s = 0.0f, sq = 0.0f;
#pragma unroll
    for (int i = 0; i < 4; ++i) {
        const int c = tid + i * 256;
        const float x = a[base + c] + r[base + c];
        v[i] = x; s += x; sq += x * x;
    }
#pragma unroll
    for (int o = 16; o; o >>= 1) {
        s  += __shfl_xor_sync(0xffffffffu, s,  o);
        sq += __shfl_xor_sync(0xffffffffu, sq, o);
    }
    if (lane == 0) { rs[warp] = s; rq[warp] = sq; }
    __syncthreads();
    if (tid < 32) {
        float s2 = (tid < 8) ? rs[tid] : 0.0f;
        float q2 = (tid < 8) ? rq[tid] : 0.0f;
#pragma unroll
        for (int o = 4; o; o >>= 1) {
            s2 += __shfl_xor_sync(0xffffffffu, s2, o);
            q2 += __shfl_xor_sync(0xffffffffu, q2, o);
        }
        if (tid == 0) { fin[0] = s2; fin[1] = q2; }
    }
    __syncthreads();
    const float mean = fin[0] * (1.0f / 1024.0f);
    float var = fin[1] * (1.0f / 1024.0f) - mean * mean;
    var = fmaxf(var, 0.0f);
    const float inv = rsqrtf(var + 1e-6f);
#pragma unroll
    for (int i = 0; i < 4; ++i) {
        const int c = tid + i * 256;
        const float y = (v[i] - mean) * inv * gw[c] + bw[c];
        out[base + c] = y;
        if (out_tf) out_tf[base + c] = f2tff(y);
    }
}

// ---------------- gated = tf32(relu(g1) * g2) (into g1) ---------------------
__global__ void gated_mul(float* __restrict__ a, const float* __restrict__ b)
{
    const long long i = ((long long)blockIdx.x * 256 + threadIdx.x) * 4;
    float4 x = *(const float4*)(a + i);
    const float4 y = *(const float4*)(b + i);
    x.x = f2tff(fmaxf(x.x, 0.0f) * y.x);
    x.y = f2tff(fmaxf(x.y, 0.0f) * y.y);
    x.z = f2tff(fmaxf(x.z, 0.0f) * y.z);
    x.w = f2tff(fmaxf(x.w, 0.0f) * y.w);
    *(float4*)(a + i) = x;
}

} // namespace stb

// ---------------------------------------------------------------------------
extern "C" void kernel_launch(void* const* d_in, const int* in_sizes, int n_in,
                              void* d_out, int out_size)
{
    using namespace stb;
    (void)in_sizes; (void)n_in; (void)out_size;

    const float* state = (const float*)d_in[0];
    const float* input = (const float*)d_in[1];
    const float* Wk    = (const float*)d_in[2];
    const float* bk    = (const float*)d_in[3];
    const float* Wv    = (const float*)d_in[4];
    const float* bv    = (const float*)d_in[5];
    const float* Wq    = (const float*)d_in[6];
    const float* bq    = (const float*)d_in[7];
    const float* Wo    = (const float*)d_in[8];
    const float* bo    = (const float*)d_in[9];
    const float* ln1g  = (const float*)d_in[10];
    const float* ln1b  = (const float*)d_in[11];
    const float* Wi    = (const float*)d_in[12];
    const float* bi    = (const float*)d_in[13];
    const float* Wg    = (const float*)d_in[14];
    const float* bg    = (const float*)d_in[15];
    const float* Wl    = (const float*)d_in[16];
    const float* bl    = (const float*)d_in[17];
    const float* Wf    = (const float*)d_in[18];
    const float* bf    = (const float*)d_in[19];
    const float* ln2g  = (const float*)d_in[20];
    const float* ln2b  = (const float*)d_in[21];
    float* out = (float*)d_out;

    float *pk, *pv, *pq, *ps, *pcat, *pt1, *px, *pxt, *pin, *pg1, *pg2;
    float *cst, *cin, *cWk, *cWv, *cWq, *cWo, *cWi, *cWg, *cWl, *cWf;
    cudaGetSymbolAddress((void**)&pk,   g_k);
    cudaGetSymbolAddress((void**)&pv,   g_v);
    cudaGetSymbolAddress((void**)&pq,   g_q);
    cudaGetSymbolAddress((void**)&ps,   g_s);
    cudaGetSymbolAddress((void**)&pcat, g_cat);
    cudaGetSymbolAddress((void**)&pt1,  g_t1);
    cudaGetSymbolAddress((void**)&px,   g_x);
    cudaGetSymbolAddress((void**)&pxt,  g_xt);
    cudaGetSymbolAddress((void**)&pin,  g_in);
    cudaGetSymbolAddress((void**)&pg1,  g_g1);
    cudaGetSymbolAddress((void**)&pg2,  g_g2);
    cudaGetSymbolAddress((void**)&cst,  g_cst);
    cudaGetSymbolAddress((void**)&cin,  g_cin);
    cudaGetSymbolAddress((void**)&cWk,  g_cWk);
    cudaGetSymbolAddress((void**)&cWv,  g_cWv);
    cudaGetSymbolAddress((void**)&cWq,  g_cWq);
    cudaGetSymbolAddress((void**)&cWo,  g_cWo);
    cudaGetSymbolAddress((void**)&cWi,  g_cWi);
    cudaGetSymbolAddress((void**)&cWg,  g_cWg);
    cudaGetSymbolAddress((void**)&cWl,  g_cWl);
    cudaGetSymbolAddress((void**)&cWf,  g_cWf);

    // opt-in to >48KB dynamic smem for each instantiation used
    cudaFuncSetAttribute(gemm_tf32<AMODE_CONCAT, BMODE_N, false, true>,
                         cudaFuncAttributeMaxDynamicSharedMemorySize, SMEM_N_BYTES);
    cudaFuncSetAttribute(gemm_tf32<AMODE_DIRECT, BMODE_N, false, true>,
                         cudaFuncAttributeMaxDynamicSharedMemorySize, SMEM_N_BYTES);
    cudaFuncSetAttribute(gemm_tf32<AMODE_DIRECT, BMODE_N, false, false>,
                         cudaFuncAttributeMaxDynamicSharedMemorySize, SMEM_N_BYTES);
    cudaFuncSetAttribute(gemm_tf32<AMODE_DIRECT, BMODE_N, true, true>,
                         cudaFuncAttributeMaxDynamicSharedMemorySize, SMEM_N_BYTES);
    cudaFuncSetAttribute(gemm_tf32<AMODE_DIRECT, BMODE_T, false, false>,
                         cudaFuncAttributeMaxDynamicSharedMemorySize, SMEM_T_BYTES);

    const long long LL512x1024  = 512LL * 1024;
    const long long LL512x2048  = 512LL * 2048;
    const long long LL2048x1024 = 2048LL * 1024;

    // 0: pre-convert constant operands to tf32 (elementwise, HBM-cheap)
    cvt_tf32<<<Bn * S_ST  * Dn / 1024, 256>>>(state, cst);
    cvt_tf32<<<Bn * S_INP * Dn / 1024, 256>>>(input, cin);
    cvt_tf32<<<Dn * Dn / 1024, 256>>>(Wk, cWk);
    cvt_tf32<<<Dn * Dn / 1024, 256>>>(Wv, cWv);
    cvt_tf32<<<Hn * Dn * Dn / 1024, 256>>>(Wq, cWq);
    cvt_tf32<<<Hn * Dn * Dn / 1024, 256>>>(Wo, cWo);
    cvt_tf32<<<Dn * Fn / 1024, 256>>>(Wi, cWi);
    cvt_tf32<<<Fn * Fn / 1024, 256>>>(Wg, cWg);
    cvt_tf32<<<Fn * Fn / 1024, 256>>>(Wl, cWl);
    cvt_tf32<<<Fn * Dn / 1024, 256>>>(Wf, cWf);

    // 1-2: k, v = concat(state,input) @ W + b  -> tf32 outputs
    gemm_tf32<AMODE_CONCAT, BMODE_N, false, true><<<dim3(8, 64, 1), NTHREADS, SMEM_N_BYTES>>>(
        cst, cin, cWk, bk, pk, 8192, 1024, 1024, 1024, 1024, 1024,
        1, 0, 0, 0, 0, 0, 0, 0, 1.0f);
    gemm_tf32<AMODE_CONCAT, BMODE_N, false, true><<<dim3(8, 64, 1), NTHREADS, SMEM_N_BYTES>>>(
        cst, cin, cWv, bv, pv, 8192, 1024, 1024, 1024, 1024, 1024,
        1, 0, 0, 0, 0, 0, 0, 0, 1.0f);

    // 3: q[b,h] = state[b] @ Wq[h] + bq[h]  -> tf32
    gemm_tf32<AMODE_DIRECT, BMODE_N, false, true><<<dim3(8, 4, 32), NTHREADS, SMEM_N_BYTES>>>(
        cst, (const float*)0, cWq, bq, pq, 512, 1024, 1024, 1024, 1024, 1024,
        8, LL512x1024, 0, 0, 1024LL * 1024, 8 * LL512x1024, LL512x1024, 1024, 1.0f);

    // 4: scores = q @ k^T / 32  (fp32 out for softmax)
    gemm_tf32<AMODE_DIRECT, BMODE_T, false, false><<<dim3(16, 4, 32), NTHREADS, SMEM_T_BYTES>>>(
        pq, (const float*)0, pk, (const float*)0, ps, 512, 2048, 1024, 1024, 1024, 2048,
        8, 8 * LL512x1024, LL512x1024, LL2048x1024, 0, 8 * LL512x2048, LL512x2048, 0,
        0.03125f);

    // 5: softmax (writes tf32 probs)
    softmax2048<<<4 * 8 * 512, 256>>>(ps);

    // 6: ctx = attn @ v  -> concat layout, tf32 out (feeds Wo)
    gemm_tf32<AMODE_DIRECT, BMODE_N, false, true><<<dim3(8, 4, 32), NTHREADS, SMEM_N_BYTES>>>(
        ps, (const float*)0, pv, (const float*)0, pcat, 512, 1024, 2048, 2048, 1024, 8192,
        8, 8 * LL512x2048, LL512x2048, LL2048x1024, 0, 512LL * 8192, 1024, 0, 1.0f);

    // 7: attn_out = concat @ Wo + bo  (fp32 out for LN)
    gemm_tf32<AMODE_DIRECT, BMODE_N, false, false><<<dim3(8, 16, 1), NTHREADS, SMEM_N_BYTES>>>(
        pcat, (const float*)0, cWo, bo, pt1, 2048, 1024, 8192, 8192, 1024, 1024,
        1, 0, 0, 0, 0, 0, 0, 0, 1.0f);

    // 8: x = LN(attn_out + state); also write tf32 twin for Wi
    add_ln1024<<<2048, 256>>>(pt1, state, ln1g, ln1b, px, pxt);

    // 9: inner = relu(x @ Wi + bi)  -> tf32 (feeds Wg/Wl)
    gemm_tf32<AMODE_DIRECT, BMODE_N, true, true><<<dim3(32, 16, 1), NTHREADS, SMEM_N_BYTES>>>(
        pxt, (const float*)0, cWi, bi, pin, 2048, 4096, 1024, 1024, 4096, 4096,
        1, 0, 0, 0, 0, 0, 0, 0, 1.0f);

    // 10-11: g1 = inner @ Wg + bg ; g2 = inner @ Wl + bl (fp32 outs)
    gemm_tf32<AMODE_DIRECT, BMODE_N, false, false><<<dim3(32, 16, 1), NTHREADS, SMEM_N_BYTES>>>(
        pin, (const float*)0, cWg, bg, pg1, 2048, 4096, 4096, 4096, 4096, 4096,
        1, 0, 0, 0, 0, 0, 0, 0, 1.0f);
    gemm_tf32<AMODE_DIRECT, BMODE_N, false, false><<<dim3(32, 16, 1), NTHREADS, SMEM_N_BYTES>>>(
        pin, (const float*)0, cWl, bl, pg2, 2048, 4096, 4096, 4096, 4096, 4096,
        1, 0, 0, 0, 0, 0, 0, 0, 1.0f);

    // 12: gated = tf32(relu(g1) * g2) (into g1; feeds Wf)
    gated_mul<<<8192, 256>>>(pg1, pg2);

    // 13: ff = gated @ Wf + bf  (fp32 out for LN)
    gemm_tf32<AMODE_DIRECT, BMODE_N, false, false><<<dim3(8, 16, 1), NTHREADS, SMEM_N_BYTES>>>(
        pg1, (const float*)0, cWf, bf, pt1, 2048, 1024, 4096, 4096, 1024, 1024,
        1, 0, 0, 0, 0, 0, 0, 0, 1.0f);

    // 14: out = LN(ff + x)
    add_ln1024<<<2048, 256>>>(pt1, px, ln2g, ln2b, out, (float*)0);
}